// round 1
// baseline (speedup 1.0000x reference)
#include <cuda_runtime.h>

#define NN 100000
#define EE 1600000
#define FD 64          // hidden feature dim
#define NHD 8          // heads
#define CDIV(a,b) (((a)+(b)-1)/(b))

// ---------------- scratch (static device arrays; no allocation) ----------------
static __device__ __align__(16) float g_dinv[NN];
static __device__ __align__(16) float g_t  [NN*FD];    // GEMM output / message source
static __device__ __align__(16) float g_acc[NN*FD];    // aggregation accumulator
static __device__ __align__(16) float g_as [NN*NHD];
static __device__ __align__(16) float g_ad [NN*NHD];
static __device__ __align__(16) float g_m  [NN*NHD];   // segment max (encoded uint, then float)
static __device__ __align__(16) float g_z  [NN*NHD];   // softmax denom, then its reciprocal
static __device__ __align__(16) float g_ps [NN*NHD];   // self-loop exp term
static __device__ __align__(16) float g_p  [EE*NHD];   // per-edge unnormalized attention

// ---------------- helpers ----------------
__device__ __forceinline__ unsigned fenc(float f) {
    unsigned u = __float_as_uint(f);
    return (u & 0x80000000u) ? ~u : (u | 0x80000000u);
}
__device__ __forceinline__ float fdec(unsigned u) {
    return (u & 0x80000000u) ? __uint_as_float(u & 0x7fffffffu) : __uint_as_float(~u);
}
__device__ __forceinline__ float lrelu(float x) { return x > 0.f ? x : 0.2f * x; }

__device__ __forceinline__ void red4(float* p, float4 v) {
    asm volatile("red.global.add.v4.f32 [%0], {%1,%2,%3,%4};"
                 :: "l"(p), "f"(v.x), "f"(v.y), "f"(v.z), "f"(v.w) : "memory");
}

// ---------------- degree / normalization ----------------
__global__ void k_deg_init() {
    int i = blockIdx.x * blockDim.x + threadIdx.x;
    if (i < NN) g_dinv[i] = 1.0f;   // self loop
}
__global__ void k_deg_edges(const int* __restrict__ dst) {
    int e = blockIdx.x * blockDim.x + threadIdx.x;
    if (e < EE) atomicAdd(&g_dinv[dst[e]], 1.0f);
}
__global__ void k_dinv() {
    int i = blockIdx.x * blockDim.x + threadIdx.x;
    if (i < NN) g_dinv[i] = rsqrtf(g_dinv[i]);
}

// ---------------- GEMM: [NN,K] x [K,64] -> [NN,64] ----------------
template<int K>
__global__ void __launch_bounds__(128) k_gemm(const float* __restrict__ A,
                                              const float* __restrict__ W,
                                              float* __restrict__ O) {
    __shared__ float4 Ws[K * 16];
    for (int i = threadIdx.x; i < K * 16; i += 128)
        Ws[i] = ((const float4*)W)[i];
    __syncthreads();
    int row = blockIdx.x * 128 + threadIdx.x;
    if (row >= NN) return;
    float4 acc[16];
#pragma unroll
    for (int j = 0; j < 16; j++) acc[j] = make_float4(0.f, 0.f, 0.f, 0.f);
    const float4* a4 = (const float4*)(A + (size_t)row * K);
#pragma unroll 2
    for (int k4 = 0; k4 < K / 4; k4++) {
        float4 a = a4[k4];
        float av[4] = {a.x, a.y, a.z, a.w};
#pragma unroll
        for (int q = 0; q < 4; q++) {
            float s = av[q];
            const float4* wr = &Ws[(k4 * 4 + q) * 16];
#pragma unroll
            for (int j = 0; j < 16; j++) {
                float4 w = wr[j];
                acc[j].x += s * w.x; acc[j].y += s * w.y;
                acc[j].z += s * w.z; acc[j].w += s * w.w;
            }
        }
    }
    float4* o4 = (float4*)(O + (size_t)row * FD);
#pragma unroll
    for (int j = 0; j < 16; j++) o4[j] = acc[j];
}

// ---------------- GCN aggregation ----------------
// acc[i] = t[i] * dinv[i]^2  (self loop term)
__global__ void k_gcn_init(const float* __restrict__ t, float* __restrict__ acc) {
    int idx = blockIdx.x * blockDim.x + threadIdx.x;
    if (idx >= NN * 16) return;
    int i = idx >> 4, c = idx & 15;
    float nv = g_dinv[i]; nv *= nv;
    float4 v = ((const float4*)t)[i * 16 + c];
    v.x *= nv; v.y *= nv; v.z *= nv; v.w *= nv;
    ((float4*)acc)[i * 16 + c] = v;
}
__global__ void k_gcn_edges(const float* __restrict__ t, float* __restrict__ acc,
                            const int* __restrict__ src, const int* __restrict__ dst) {
    int idx = blockIdx.x * blockDim.x + threadIdx.x;
    if (idx >= EE * 16) return;
    int e = idx >> 4, c = idx & 15;
    int s = src[e], d = dst[e];
    float nrm = g_dinv[s] * g_dinv[d];
    float4 v = ((const float4*)t)[s * 16 + c];
    v.x *= nrm; v.y *= nrm; v.z *= nrm; v.w *= nrm;
    red4(acc + (size_t)d * FD + c * 4, v);
}
__global__ void k_bias_act(float* __restrict__ acc, const float* __restrict__ b, int do_relu) {
    int idx = blockIdx.x * blockDim.x + threadIdx.x;
    if (idx >= NN * FD) return;
    float v = acc[idx] + b[idx & 63];
    if (do_relu) v = fmaxf(v, 0.f);
    acc[idx] = v;
}

// ---------------- GAT ----------------
__global__ void k_alphas(const float* __restrict__ hg, const float* __restrict__ Asrc,
                         const float* __restrict__ Adst) {
    int i = blockIdx.x * blockDim.x + threadIdx.x;
    if (i >= NN) return;
    const float4* h4 = (const float4*)(hg + (size_t)i * FD);
#pragma unroll
    for (int h = 0; h < NHD; h++) {
        float4 a0 = h4[h * 2], a1 = h4[h * 2 + 1];
        float4 s0 = ((const float4*)Asrc)[h * 2], s1 = ((const float4*)Asrc)[h * 2 + 1];
        float4 t0 = ((const float4*)Adst)[h * 2], t1 = ((const float4*)Adst)[h * 2 + 1];
        g_as[i * NHD + h] = a0.x*s0.x + a0.y*s0.y + a0.z*s0.z + a0.w*s0.w
                          + a1.x*s1.x + a1.y*s1.y + a1.z*s1.z + a1.w*s1.w;
        g_ad[i * NHD + h] = a0.x*t0.x + a0.y*t0.y + a0.z*t0.z + a0.w*t0.w
                          + a1.x*t1.x + a1.y*t1.y + a1.z*t1.z + a1.w*t1.w;
    }
}
// m initialized with the self-loop edge score (encoded for int atomicMax)
__global__ void k_m_init() {
    int idx = blockIdx.x * blockDim.x + threadIdx.x;
    if (idx >= NN * NHD) return;
    float e = lrelu(g_as[idx] + g_ad[idx]);
    g_m[idx] = __uint_as_float(fenc(e));
}
__global__ void k_gatA(const int* __restrict__ src, const int* __restrict__ dst) {
    int e = blockIdx.x * blockDim.x + threadIdx.x;
    if (e >= EE) return;
    int s = src[e], d = dst[e];
    const float* as = g_as + (size_t)s * NHD;
    const float* ad = g_ad + (size_t)d * NHD;
    unsigned* mp = (unsigned*)(g_m + (size_t)d * NHD);
#pragma unroll
    for (int h = 0; h < NHD; h++)
        atomicMax(mp + h, fenc(lrelu(as[h] + ad[h])));
}
// decode m, init z and self-exp
__global__ void k_z_init() {
    int idx = blockIdx.x * blockDim.x + threadIdx.x;
    if (idx >= NN * NHD) return;
    float m = fdec(__float_as_uint(g_m[idx]));
    g_m[idx] = m;
    float zs = __expf(lrelu(g_as[idx] + g_ad[idx]) - m);
    g_z[idx] = zs;
    g_ps[idx] = zs;
}
__global__ void k_gatB(const int* __restrict__ src, const int* __restrict__ dst) {
    int e = blockIdx.x * blockDim.x + threadIdx.x;
    if (e >= EE) return;
    int s = src[e], d = dst[e];
    const float* as = g_as + (size_t)s * NHD;
    const float* ad = g_ad + (size_t)d * NHD;
    const float* mm = g_m + (size_t)d * NHD;
    float* zz = g_z + (size_t)d * NHD;
    float p[NHD];
#pragma unroll
    for (int h = 0; h < NHD; h++) {
        p[h] = __expf(lrelu(as[h] + ad[h]) - mm[h]);
        atomicAdd(zz + h, p[h]);
    }
    float4* pp = (float4*)(g_p + (size_t)e * NHD);
    pp[0] = make_float4(p[0], p[1], p[2], p[3]);
    pp[1] = make_float4(p[4], p[5], p[6], p[7]);
}
__global__ void k_zinv() {
    int idx = blockIdx.x * blockDim.x + threadIdx.x;
    if (idx >= NN * NHD) return;
    g_z[idx] = 1.0f / g_z[idx];
}
// acc init with self-loop term: alpha_self * hg[i]
__global__ void k_gat_acc_init(const float* __restrict__ hg, float* __restrict__ acc) {
    int idx = blockIdx.x * blockDim.x + threadIdx.x;
    if (idx >= NN * 16) return;
    int i = idx >> 4, c = idx & 15, h = c >> 1;
    float a = g_ps[i * NHD + h] * g_z[i * NHD + h];
    float4 v = ((const float4*)hg)[i * 16 + c];
    v.x *= a; v.y *= a; v.z *= a; v.w *= a;
    ((float4*)acc)[i * 16 + c] = v;
}
__global__ void k_gatC(const float* __restrict__ hg, float* __restrict__ acc,
                       const int* __restrict__ src, const int* __restrict__ dst) {
    int idx = blockIdx.x * blockDim.x + threadIdx.x;
    if (idx >= EE * 16) return;
    int e = idx >> 4, c = idx & 15, h = c >> 1;
    int s = src[e], d = dst[e];
    float a = g_p[(size_t)e * NHD + h] * g_z[(size_t)d * NHD + h];
    float4 v = ((const float4*)hg)[s * 16 + c];
    v.x *= a; v.y *= a; v.z *= a; v.w *= a;
    red4(acc + (size_t)d * FD + c * 4, v);
}

// ---------------- driver ----------------
extern "C" void kernel_launch(void* const* d_in, const int* in_sizes, int n_in,
                              void* d_out, int out_size) {
    const float* x    = (const float*)d_in[0];
    const int*   ei   = (const int*)d_in[1];
    const float* W0   = (const float*)d_in[2];
    const float* b0   = (const float*)d_in[3];
    const float* Wg   = (const float*)d_in[4];
    const float* Asrc = (const float*)d_in[5];
    const float* Adst = (const float*)d_in[6];
    const float* bg   = (const float*)d_in[7];
    const float* W2   = (const float*)d_in[8];
    const float* b2   = (const float*)d_in[9];
    const float* W3   = (const float*)d_in[10];
    const float* b3   = (const float*)d_in[11];
    const int* src = ei;
    const int* dst = ei + EE;

    float* t;   cudaGetSymbolAddress((void**)&t,   g_t);
    float* acc; cudaGetSymbolAddress((void**)&acc, g_acc);
    float* outp = (float*)d_out;

    const int T = 256;
    const int gN    = CDIV(NN, T);
    const int gE    = CDIV(EE, T);
    const int gN8   = CDIV(NN * NHD, T);
    const int gN16  = CDIV(NN * 16, T);
    const int gN64  = CDIV(NN * FD, T);
    const int gE16  = CDIV(EE * 16, T);
    const int gGemm = CDIV(NN, 128);

    // degrees (graph is static across layers)
    k_deg_init<<<gN, T>>>();
    k_deg_edges<<<gE, T>>>(dst);
    k_dinv<<<gN, T>>>();

    // ---- layer 0: GCN(128->64) + relu ----
    k_gemm<128><<<gGemm, 128>>>(x, W0, t);
    k_gcn_init<<<gN16, T>>>(t, acc);
    k_gcn_edges<<<gE16, T>>>(t, acc, src, dst);
    k_bias_act<<<gN64, T>>>(acc, b0, 1);          // acc = h1

    // ---- layer 1: GAT(64 -> 8x8 concat) + relu ----
    k_gemm<64><<<gGemm, 128>>>(acc, Wg, t);       // t = hg
    k_alphas<<<gN, T>>>(t, Asrc, Adst);
    k_m_init<<<gN8, T>>>();
    k_gatA<<<gE, T>>>(src, dst);
    k_z_init<<<gN8, T>>>();
    k_gatB<<<gE, T>>>(src, dst);
    k_zinv<<<gN8, T>>>();
    k_gat_acc_init<<<gN16, T>>>(t, acc);
    k_gatC<<<gE16, T>>>(t, acc, src, dst);
    k_bias_act<<<gN64, T>>>(acc, bg, 1);          // acc = h2

    // ---- layer 2: GCN(64->64) + relu ----
    k_gemm<64><<<gGemm, 128>>>(acc, W2, t);
    k_gcn_init<<<gN16, T>>>(t, acc);
    k_gcn_edges<<<gE16, T>>>(t, acc, src, dst);
    k_bias_act<<<gN64, T>>>(acc, b2, 1);          // acc = h3

    // ---- layer 3: GCN(64->64), no relu, into d_out ----
    k_gemm<64><<<gGemm, 128>>>(acc, W3, t);
    k_gcn_init<<<gN16, T>>>(t, outp);
    k_gcn_edges<<<gE16, T>>>(t, outp, src, dst);
    k_bias_act<<<gN64, T>>>(outp, b3, 0);
}

// round 3
// speedup vs baseline: 1.7505x; 1.7505x over previous
#include <cuda_runtime.h>

#define NN 100000
#define EE 1600000
#define FD 64
#define NHD 8
#define NB  391               // CDIV(NN,256) scan blocks
#define CDIV(a,b) (((a)+(b)-1)/(b))

// ---------------- scratch ----------------
static __device__ __align__(16) float g_dinv[NN];
static __device__ __align__(16) float g_t  [NN*FD];
static __device__ __align__(16) float g_acc[NN*FD];
static __device__ __align__(16) float g_as [NN*NHD];
static __device__ __align__(16) float g_ad [NN*NHD];
static __device__ int g_deg[NN];
static __device__ int g_rowptr[NN+1];
static __device__ int g_cursor[NN];
static __device__ int g_csrc[EE];
static __device__ int g_bsum[512];

__device__ __forceinline__ float lrelu(float x) { return x > 0.f ? x : 0.2f * x; }

// ---------------- CSR build ----------------
__global__ void k_deg_zero() {
    int i = blockIdx.x * blockDim.x + threadIdx.x;
    if (i < NN) g_deg[i] = 0;
}
__global__ void k_deg(const int* __restrict__ dst) {
    int e = blockIdx.x * blockDim.x + threadIdx.x;
    if (e < EE) atomicAdd(&g_deg[dst[e]], 1);
}
__global__ void k_dinv() {
    int i = blockIdx.x * blockDim.x + threadIdx.x;
    if (i < NN) g_dinv[i] = rsqrtf((float)(g_deg[i] + 1));   // +1 self loop
}
__global__ void __launch_bounds__(256) k_scan1() {
    int i = blockIdx.x * 256 + threadIdx.x;
    int v = (i < NN) ? g_deg[i] : 0;
    int lane = threadIdx.x & 31, wid = threadIdx.x >> 5;
    int x = v;
#pragma unroll
    for (int o = 1; o < 32; o <<= 1) { int y = __shfl_up_sync(~0u, x, o); if (lane >= o) x += y; }
    __shared__ int ws[8];
    if (lane == 31) ws[wid] = x;
    __syncthreads();
    if (wid == 0) {
        int t = (lane < 8) ? ws[lane] : 0;
#pragma unroll
        for (int o = 1; o < 8; o <<= 1) { int y = __shfl_up_sync(~0u, t, o); if (lane >= o) t += y; }
        if (lane < 8) ws[lane] = t;
    }
    __syncthreads();
    int base = wid > 0 ? ws[wid - 1] : 0;
    int incl = x + base;
    if (i < NN) g_rowptr[i] = incl - v;
    if (threadIdx.x == 255) g_bsum[blockIdx.x] = incl;
}
__global__ void __launch_bounds__(512) k_scan2() {
    int i = threadIdx.x;
    int v = (i < NB) ? g_bsum[i] : 0;
    int lane = i & 31, wid = i >> 5;
    int x = v;
#pragma unroll
    for (int o = 1; o < 32; o <<= 1) { int y = __shfl_up_sync(~0u, x, o); if (lane >= o) x += y; }
    __shared__ int ws[16];
    if (lane == 31) ws[wid] = x;
    __syncthreads();
    if (wid == 0) {
        int t = (lane < 16) ? ws[lane] : 0;
#pragma unroll
        for (int o = 1; o < 16; o <<= 1) { int y = __shfl_up_sync(~0u, t, o); if (lane >= o) t += y; }
        if (lane < 16) ws[lane] = t;
    }
    __syncthreads();
    int base = wid > 0 ? ws[wid - 1] : 0;
    if (i < NB) g_bsum[i] = x + base - v;   // exclusive
}
__global__ void k_scan3() {
    int i = blockIdx.x * blockDim.x + threadIdx.x;
    if (i < NN) {
        int r = g_rowptr[i] + g_bsum[i >> 8];
        g_rowptr[i] = r;
        g_cursor[i] = r;
    }
    if (i == 0) g_rowptr[NN] = EE;
}
__global__ void k_scatter(const int* __restrict__ src, const int* __restrict__ dst) {
    int e = blockIdx.x * blockDim.x + threadIdx.x;
    if (e >= EE) return;
    int pos = atomicAdd(&g_cursor[dst[e]], 1);
    g_csrc[pos] = src[e];
}

// ---------------- GEMM: [NN,K] x [K,64] -> [NN,64], optional dinv-row scaling ----------------
template<int K, int SCALE>
__global__ void __launch_bounds__(128) k_gemm(const float* __restrict__ A,
                                              const float* __restrict__ W,
                                              float* __restrict__ O) {
    __shared__ float4 Ws[K * 16];
    for (int i = threadIdx.x; i < K * 16; i += 128)
        Ws[i] = ((const float4*)W)[i];
    __syncthreads();
    int row = blockIdx.x * 128 + threadIdx.x;
    if (row >= NN) return;
    float4 acc[16];
#pragma unroll
    for (int j = 0; j < 16; j++) acc[j] = make_float4(0.f, 0.f, 0.f, 0.f);
    const float4* a4 = (const float4*)(A + (size_t)row * K);
#pragma unroll 2
    for (int k4 = 0; k4 < K / 4; k4++) {
        float4 a = a4[k4];
        float av[4] = {a.x, a.y, a.z, a.w};
#pragma unroll
        for (int q = 0; q < 4; q++) {
            float s = av[q];
            const float4* wr = &Ws[(k4 * 4 + q) * 16];
#pragma unroll
            for (int j = 0; j < 16; j++) {
                float4 w = wr[j];
                acc[j].x += s * w.x; acc[j].y += s * w.y;
                acc[j].z += s * w.z; acc[j].w += s * w.w;
            }
        }
    }
    float sc = SCALE ? g_dinv[row] : 1.0f;
    float4* o4 = (float4*)(O + (size_t)row * FD);
#pragma unroll
    for (int j = 0; j < 16; j++) {
        float4 v = acc[j];
        v.x *= sc; v.y *= sc; v.z *= sc; v.w *= sc;
        o4[j] = v;
    }
}

// ---------------- GCN gather (warp per node) ----------------
// ts[i] = dinv[i] * (x@W)[i]. out[d] = dinv[d]*(sum_{s in N(d)} ts[s] + ts[d]) + b, optional relu.
__global__ void __launch_bounds__(256) k_gcn_gather(const float* __restrict__ ts,
                                                    float* __restrict__ out,
                                                    const float* __restrict__ b,
                                                    int do_relu) {
    int warp = (blockIdx.x * blockDim.x + threadIdx.x) >> 5;
    int lane = threadIdx.x & 31;
    if (warp >= NN) return;
    int d = warp;
    int beg = g_rowptr[d], end = g_rowptr[d + 1];
    float2 acc = ((const float2*)(ts + (size_t)d * FD))[lane];   // self term
    for (int base = beg; base < end; base += 32) {
        int n = min(32, end - base);
        int s_l = (lane < n) ? g_csrc[base + lane] : 0;
        for (int j = 0; j < n; j++) {
            int s = __shfl_sync(0xffffffffu, s_l, j);
            float2 v = ((const float2*)(ts + (size_t)s * FD))[lane];
            acc.x += v.x; acc.y += v.y;
        }
    }
    float nv = g_dinv[d];
    float2 bb = ((const float2*)b)[lane];
    float ox = acc.x * nv + bb.x, oy = acc.y * nv + bb.y;
    if (do_relu) { ox = fmaxf(ox, 0.f); oy = fmaxf(oy, 0.f); }
    ((float2*)(out + (size_t)d * FD))[lane] = make_float2(ox, oy);
}

// ---------------- GAT ----------------
__global__ void k_alphas(const float* __restrict__ hg, const float* __restrict__ Asrc,
                         const float* __restrict__ Adst) {
    int i = blockIdx.x * blockDim.x + threadIdx.x;
    if (i >= NN) return;
    const float4* h4 = (const float4*)(hg + (size_t)i * FD);
#pragma unroll
    for (int h = 0; h < NHD; h++) {
        float4 a0 = h4[h * 2], a1 = h4[h * 2 + 1];
        float4 s0 = ((const float4*)Asrc)[h * 2], s1 = ((const float4*)Asrc)[h * 2 + 1];
        float4 t0 = ((const float4*)Adst)[h * 2], t1 = ((const float4*)Adst)[h * 2 + 1];
        g_as[i * NHD + h] = a0.x*s0.x + a0.y*s0.y + a0.z*s0.z + a0.w*s0.w
                          + a1.x*s1.x + a1.y*s1.y + a1.z*s1.z + a1.w*s1.w;
        g_ad[i * NHD + h] = a0.x*t0.x + a0.y*t0.y + a0.z*t0.z + a0.w*t0.w
                          + a1.x*t1.x + a1.y*t1.y + a1.z*t1.z + a1.w*t1.w;
    }
}

// Fully fused GAT: online-softmax over incoming edges + weighted gather. Warp per node.
__global__ void __launch_bounds__(256) k_gat(const float* __restrict__ hg,
                                             float* __restrict__ out,
                                             const float* __restrict__ bg) {
    int warp = (blockIdx.x * blockDim.x + threadIdx.x) >> 5;
    int lane = threadIdx.x & 31;
    if (warp >= NN) return;
    int d = warp;
    int beg = g_rowptr[d], end = g_rowptr[d + 1];

    // broadcast loads of ad[d][*] and as[d][*]
    float4 ad0 = ((const float4*)(g_ad + (size_t)d * NHD))[0];
    float4 ad1 = ((const float4*)(g_ad + (size_t)d * NHD))[1];
    float4 asd0 = ((const float4*)(g_as + (size_t)d * NHD))[0];
    float4 asd1 = ((const float4*)(g_as + (size_t)d * NHD))[1];
    float adh[8] = {ad0.x, ad0.y, ad0.z, ad0.w, ad1.x, ad1.y, ad1.z, ad1.w};
    float ssf[8] = {lrelu(asd0.x+ad0.x), lrelu(asd0.y+ad0.y), lrelu(asd0.z+ad0.z), lrelu(asd0.w+ad0.w),
                    lrelu(asd1.x+ad1.x), lrelu(asd1.y+ad1.y), lrelu(asd1.z+ad1.z), lrelu(asd1.w+ad1.w)};

    // ---- phase 1: online softmax stats (lane-parallel over edges) ----
    float m[8], z[8];
#pragma unroll
    for (int h = 0; h < 8; h++) { m[h] = -1e30f; z[h] = 0.f; }
    if (lane == 0) {   // self-loop edge
#pragma unroll
        for (int h = 0; h < 8; h++) { m[h] = ssf[h]; z[h] = 1.f; }
    }
    for (int idx = beg + lane; idx < end; idx += 32) {
        int s = g_csrc[idx];
        float4 v0 = ((const float4*)(g_as + (size_t)s * NHD))[0];
        float4 v1 = ((const float4*)(g_as + (size_t)s * NHD))[1];
        float sc[8] = {lrelu(v0.x+adh[0]), lrelu(v0.y+adh[1]), lrelu(v0.z+adh[2]), lrelu(v0.w+adh[3]),
                       lrelu(v1.x+adh[4]), lrelu(v1.y+adh[5]), lrelu(v1.z+adh[6]), lrelu(v1.w+adh[7])};
#pragma unroll
        for (int h = 0; h < 8; h++) {
            float mn = fmaxf(m[h], sc[h]);
            z[h] = z[h] * __expf(m[h] - mn) + __expf(sc[h] - mn);
            m[h] = mn;
        }
    }
    // warp merge of (m, z)
#pragma unroll
    for (int o = 16; o > 0; o >>= 1) {
#pragma unroll
        for (int h = 0; h < 8; h++) {
            float mo = __shfl_xor_sync(0xffffffffu, m[h], o);
            float zo = __shfl_xor_sync(0xffffffffu, z[h], o);
            float mn = fmaxf(m[h], mo);
            z[h] = z[h] * __expf(m[h] - mn) + zo * __expf(mo - mn);
            m[h] = mn;
        }
    }
    float zi[8];
#pragma unroll
    for (int h = 0; h < 8; h++) zi[h] = 1.0f / z[h];

    // per-lane scalars: my feature pair belongs to head lane>>2; lanes 0-7 also score head=lane
    int hmy = lane >> 2;
    float m_my = 0.f, zi_my = 0.f, m_l = 0.f, zi_l = 0.f, ad_l = 0.f;
#pragma unroll
    for (int h = 0; h < 8; h++) {
        if (hmy == h) { m_my = m[h]; zi_my = zi[h]; }
        if (lane == h) { m_l = m[h]; zi_l = zi[h]; ad_l = adh[h]; }
    }

    // ---- phase 2: weighted aggregation (feature-parallel) ----
    float p_self = 0.f;
#pragma unroll
    for (int h = 0; h < 8; h++) if (hmy == h) p_self = __expf(ssf[h] - m[h]) * zi[h];
    float2 hv = ((const float2*)(hg + (size_t)d * FD))[lane];
    float2 acc = make_float2(p_self * hv.x, p_self * hv.y);

    for (int base = beg; base < end; base += 32) {
        int n = min(32, end - base);
        int s_l = (lane < n) ? g_csrc[base + lane] : 0;
        for (int j = 0; j < n; j++) {
            int s = __shfl_sync(0xffffffffu, s_l, j);
            float p = 0.f;
            if (lane < 8) {
                float asv = g_as[(size_t)s * NHD + lane];
                p = __expf(lrelu(asv + ad_l) - m_l) * zi_l;
            }
            float pmy = __shfl_sync(0xffffffffu, p, hmy);
            float2 v = ((const float2*)(hg + (size_t)s * FD))[lane];
            acc.x += pmy * v.x; acc.y += pmy * v.y;
        }
    }
    float2 bb = ((const float2*)bg)[lane];
    float ox = fmaxf(acc.x + bb.x, 0.f);
    float oy = fmaxf(acc.y + bb.y, 0.f);
    ((float2*)(out + (size_t)d * FD))[lane] = make_float2(ox, oy);
}

// ---------------- driver ----------------
extern "C" void kernel_launch(void* const* d_in, const int* in_sizes, int n_in,
                              void* d_out, int out_size) {
    const float* x    = (const float*)d_in[0];
    const int*   ei   = (const int*)d_in[1];
    const float* W0   = (const float*)d_in[2];
    const float* b0   = (const float*)d_in[3];
    const float* Wg   = (const float*)d_in[4];
    const float* Asrc = (const float*)d_in[5];
    const float* Adst = (const float*)d_in[6];
    const float* bg   = (const float*)d_in[7];
    const float* W2   = (const float*)d_in[8];
    const float* b2   = (const float*)d_in[9];
    const float* W3   = (const float*)d_in[10];
    const float* b3   = (const float*)d_in[11];
    const int* src = ei;
    const int* dst = ei + EE;

    float* t;   cudaGetSymbolAddress((void**)&t,   g_t);
    float* acc; cudaGetSymbolAddress((void**)&acc, g_acc);
    float* outp = (float*)d_out;

    const int T = 256;
    const int gN    = CDIV(NN, T);
    const int gE    = CDIV(EE, T);
    const int gGemm = CDIV(NN, 128);
    const int gWarp = CDIV(NN * 32, T);   // warp-per-node kernels

    // ---- CSR build (graph static across layers) ----
    k_deg_zero<<<gN, T>>>();
    k_deg<<<gE, T>>>(dst);
    k_dinv<<<gN, T>>>();
    k_scan1<<<NB, 256>>>();
    k_scan2<<<1, 512>>>();
    k_scan3<<<gN, T>>>();
    k_scatter<<<gE, T>>>(src, dst);

    // ---- layer 0: GCN(128->64) + relu ----
    k_gemm<128, 1><<<gGemm, 128>>>(x, W0, t);
    k_gcn_gather<<<gWarp, T>>>(t, acc, b0, 1);

    // ---- layer 1: GAT(64 -> 8x8 concat) + relu ----
    k_gemm<64, 0><<<gGemm, 128>>>(acc, Wg, t);
    k_alphas<<<gN, T>>>(t, Asrc, Adst);
    k_gat<<<gWarp, T>>>(t, acc, bg);

    // ---- layer 2: GCN(64->64) + relu ----
    k_gemm<64, 1><<<gGemm, 128>>>(acc, W2, t);
    k_gcn_gather<<<gWarp, T>>>(t, acc, b2, 1);

    // ---- layer 3: GCN(64->64) into d_out, no relu ----
    k_gemm<64, 1><<<gGemm, 128>>>(acc, W3, t);
    k_gcn_gather<<<gWarp, T>>>(t, outp, b3, 0);
}

// round 4
// speedup vs baseline: 2.1415x; 1.2233x over previous
#include <cuda_runtime.h>

#define NN 100000
#define EE 1600000
#define FD 64
#define NHD 8
#define NB  391               // CDIV(NN,256) scan blocks
#define CDIV(a,b) (((a)+(b)-1)/(b))

// ---------------- scratch ----------------
static __device__ __align__(16) float g_dinv[NN];
static __device__ __align__(16) float g_t  [NN*FD];
static __device__ __align__(16) float g_acc[NN*FD];
static __device__ __align__(16) float g_as [NN*NHD];
static __device__ __align__(16) float g_ad [NN*NHD];
static __device__ int g_deg[NN];
static __device__ int g_rowptr[NN+1];
static __device__ int g_cursor[NN];
static __device__ int g_csrc[EE];
static __device__ int g_bsum[512];

__device__ __forceinline__ float lrelu(float x) { return x > 0.f ? x : 0.2f * x; }

// ---------------- CSR build ----------------
__global__ void k_deg_zero() {
    int i = blockIdx.x * blockDim.x + threadIdx.x;
    if (i < NN) g_deg[i] = 0;
}
__global__ void k_deg(const int* __restrict__ dst) {
    int e = blockIdx.x * blockDim.x + threadIdx.x;
    if (e < EE) atomicAdd(&g_deg[dst[e]], 1);
}
__global__ void k_dinv() {
    int i = blockIdx.x * blockDim.x + threadIdx.x;
    if (i < NN) g_dinv[i] = rsqrtf((float)(g_deg[i] + 1));   // +1 self loop
}
__global__ void __launch_bounds__(256) k_scan1() {
    int i = blockIdx.x * 256 + threadIdx.x;
    int v = (i < NN) ? g_deg[i] : 0;
    int lane = threadIdx.x & 31, wid = threadIdx.x >> 5;
    int x = v;
#pragma unroll
    for (int o = 1; o < 32; o <<= 1) { int y = __shfl_up_sync(~0u, x, o); if (lane >= o) x += y; }
    __shared__ int ws[8];
    if (lane == 31) ws[wid] = x;
    __syncthreads();
    if (wid == 0) {
        int t = (lane < 8) ? ws[lane] : 0;
#pragma unroll
        for (int o = 1; o < 8; o <<= 1) { int y = __shfl_up_sync(~0u, t, o); if (lane >= o) t += y; }
        if (lane < 8) ws[lane] = t;
    }
    __syncthreads();
    int base = wid > 0 ? ws[wid - 1] : 0;
    int incl = x + base;
    if (i < NN) g_rowptr[i] = incl - v;
    if (threadIdx.x == 255) g_bsum[blockIdx.x] = incl;
}
__global__ void __launch_bounds__(512) k_scan2() {
    int i = threadIdx.x;
    int v = (i < NB) ? g_bsum[i] : 0;
    int lane = i & 31, wid = i >> 5;
    int x = v;
#pragma unroll
    for (int o = 1; o < 32; o <<= 1) { int y = __shfl_up_sync(~0u, x, o); if (lane >= o) x += y; }
    __shared__ int ws[16];
    if (lane == 31) ws[wid] = x;
    __syncthreads();
    if (wid == 0) {
        int t = (lane < 16) ? ws[lane] : 0;
#pragma unroll
        for (int o = 1; o < 16; o <<= 1) { int y = __shfl_up_sync(~0u, t, o); if (lane >= o) t += y; }
        if (lane < 16) ws[lane] = t;
    }
    __syncthreads();
    int base = wid > 0 ? ws[wid - 1] : 0;
    if (i < NB) g_bsum[i] = x + base - v;   // exclusive
}
__global__ void k_scan3() {
    int i = blockIdx.x * blockDim.x + threadIdx.x;
    if (i < NN) {
        int r = g_rowptr[i] + g_bsum[i >> 8];
        g_rowptr[i] = r;
        g_cursor[i] = r;
    }
    if (i == 0) g_rowptr[NN] = EE;
}
__global__ void k_scatter(const int* __restrict__ src, const int* __restrict__ dst) {
    int e = blockIdx.x * blockDim.x + threadIdx.x;
    if (e >= EE) return;
    int pos = atomicAdd(&g_cursor[dst[e]], 1);
    g_csrc[pos] = src[e];
}

// ---------------- register-tiled GEMM: [NN,K] x [K,64] -> [NN,64] ----------------
// BM=128, BN=64, BK=16, 256 threads. Thread (tx,ty) computes rows ty*8..+7, cols tx*4..+3.
// W resident in smem; A staged through double-buffered transposed tile As[k][row].
template<int K, int SCALE>
__global__ void __launch_bounds__(256) k_gemm(const float* __restrict__ A,
                                              const float* __restrict__ W,
                                              float* __restrict__ O) {
    constexpr int NKB = K / 16;
    __shared__ float Ws[K * 64];
    __shared__ float As[2][16 * 128];

    const int tid = threadIdx.x;
    const int tx = tid & 15, ty = tid >> 4;
    const int lr = tid >> 2, lk = tid & 3;        // A-load: row-in-tile, k4-chunk
    const int row_blk = blockIdx.x * 128;

    // stage W (whole K x 64) into smem
    {
        const float4* W4 = (const float4*)W;
        float4* Ws4 = (float4*)Ws;
#pragma unroll
        for (int i = tid; i < K * 16; i += 256) Ws4[i] = W4[i];
    }

    const float4* A4 = (const float4*)A;
    float4 rg[2];

    // prologue: load tile kb=0
#pragma unroll
    for (int h = 0; h < 2; h++) {
        int grow = row_blk + lr + h * 64;
        rg[h] = (grow < NN) ? A4[(size_t)grow * (K / 4) + lk]
                            : make_float4(0.f, 0.f, 0.f, 0.f);
    }
#pragma unroll
    for (int h = 0; h < 2; h++) {
        int r = lr + h * 64;
        As[0][(lk * 4 + 0) * 128 + r] = rg[h].x;
        As[0][(lk * 4 + 1) * 128 + r] = rg[h].y;
        As[0][(lk * 4 + 2) * 128 + r] = rg[h].z;
        As[0][(lk * 4 + 3) * 128 + r] = rg[h].w;
    }
    __syncthreads();

    float acc[8][4];
#pragma unroll
    for (int i = 0; i < 8; i++)
#pragma unroll
        for (int j = 0; j < 4; j++) acc[i][j] = 0.f;

    for (int kb = 0; kb < NKB; kb++) {
        int b = kb & 1;
        if (kb + 1 < NKB) {
#pragma unroll
            for (int h = 0; h < 2; h++) {
                int grow = row_blk + lr + h * 64;
                rg[h] = (grow < NN) ? A4[(size_t)grow * (K / 4) + (kb + 1) * 4 + lk]
                                    : make_float4(0.f, 0.f, 0.f, 0.f);
            }
        }
#pragma unroll
        for (int k = 0; k < 16; k++) {
            float4 w = *(const float4*)&Ws[(kb * 16 + k) * 64 + tx * 4];
            float4 a0 = *(const float4*)&As[b][k * 128 + ty * 8];
            float4 a1 = *(const float4*)&As[b][k * 128 + ty * 8 + 4];
            float av[8] = {a0.x, a0.y, a0.z, a0.w, a1.x, a1.y, a1.z, a1.w};
#pragma unroll
            for (int i = 0; i < 8; i++) {
                acc[i][0] += av[i] * w.x;
                acc[i][1] += av[i] * w.y;
                acc[i][2] += av[i] * w.z;
                acc[i][3] += av[i] * w.w;
            }
        }
        if (kb + 1 < NKB) {
            int nb = (kb + 1) & 1;
#pragma unroll
            for (int h = 0; h < 2; h++) {
                int r = lr + h * 64;
                As[nb][(lk * 4 + 0) * 128 + r] = rg[h].x;
                As[nb][(lk * 4 + 1) * 128 + r] = rg[h].y;
                As[nb][(lk * 4 + 2) * 128 + r] = rg[h].z;
                As[nb][(lk * 4 + 3) * 128 + r] = rg[h].w;
            }
            __syncthreads();
        }
    }

#pragma unroll
    for (int i = 0; i < 8; i++) {
        int row = row_blk + ty * 8 + i;
        if (row < NN) {
            float sc = SCALE ? g_dinv[row] : 1.0f;
            float4 v = make_float4(acc[i][0] * sc, acc[i][1] * sc,
                                   acc[i][2] * sc, acc[i][3] * sc);
            ((float4*)(O + (size_t)row * FD))[tx] = v;
        }
    }
}

// ---------------- GCN gather (warp per node) ----------------
__global__ void __launch_bounds__(256) k_gcn_gather(const float* __restrict__ ts,
                                                    float* __restrict__ out,
                                                    const float* __restrict__ b,
                                                    int do_relu) {
    int warp = (blockIdx.x * blockDim.x + threadIdx.x) >> 5;
    int lane = threadIdx.x & 31;
    if (warp >= NN) return;
    int d = warp;
    int beg = g_rowptr[d], end = g_rowptr[d + 1];
    float2 acc = ((const float2*)(ts + (size_t)d * FD))[lane];   // self term
    for (int base = beg; base < end; base += 32) {
        int n = min(32, end - base);
        int s_l = (lane < n) ? g_csrc[base + lane] : 0;
        for (int j = 0; j < n; j++) {
            int s = __shfl_sync(0xffffffffu, s_l, j);
            float2 v = ((const float2*)(ts + (size_t)s * FD))[lane];
            acc.x += v.x; acc.y += v.y;
        }
    }
    float nv = g_dinv[d];
    float2 bb = ((const float2*)b)[lane];
    float ox = acc.x * nv + bb.x, oy = acc.y * nv + bb.y;
    if (do_relu) { ox = fmaxf(ox, 0.f); oy = fmaxf(oy, 0.f); }
    ((float2*)(out + (size_t)d * FD))[lane] = make_float2(ox, oy);
}

// ---------------- GAT ----------------
__global__ void k_alphas(const float* __restrict__ hg, const float* __restrict__ Asrc,
                         const float* __restrict__ Adst) {
    int i = blockIdx.x * blockDim.x + threadIdx.x;
    if (i >= NN) return;
    const float4* h4 = (const float4*)(hg + (size_t)i * FD);
#pragma unroll
    for (int h = 0; h < NHD; h++) {
        float4 a0 = h4[h * 2], a1 = h4[h * 2 + 1];
        float4 s0 = ((const float4*)Asrc)[h * 2], s1 = ((const float4*)Asrc)[h * 2 + 1];
        float4 t0 = ((const float4*)Adst)[h * 2], t1 = ((const float4*)Adst)[h * 2 + 1];
        g_as[i * NHD + h] = a0.x*s0.x + a0.y*s0.y + a0.z*s0.z + a0.w*s0.w
                          + a1.x*s1.x + a1.y*s1.y + a1.z*s1.z + a1.w*s1.w;
        g_ad[i * NHD + h] = a0.x*t0.x + a0.y*t0.y + a0.z*t0.z + a0.w*t0.w
                          + a1.x*t1.x + a1.y*t1.y + a1.z*t1.z + a1.w*t1.w;
    }
}

// Fully fused GAT: online-softmax over incoming edges + weighted gather. Warp per node.
__global__ void __launch_bounds__(256) k_gat(const float* __restrict__ hg,
                                             float* __restrict__ out,
                                             const float* __restrict__ bg) {
    int warp = (blockIdx.x * blockDim.x + threadIdx.x) >> 5;
    int lane = threadIdx.x & 31;
    if (warp >= NN) return;
    int d = warp;
    int beg = g_rowptr[d], end = g_rowptr[d + 1];

    float4 ad0 = ((const float4*)(g_ad + (size_t)d * NHD))[0];
    float4 ad1 = ((const float4*)(g_ad + (size_t)d * NHD))[1];
    float4 asd0 = ((const float4*)(g_as + (size_t)d * NHD))[0];
    float4 asd1 = ((const float4*)(g_as + (size_t)d * NHD))[1];
    float adh[8] = {ad0.x, ad0.y, ad0.z, ad0.w, ad1.x, ad1.y, ad1.z, ad1.w};
    float ssf[8] = {lrelu(asd0.x+ad0.x), lrelu(asd0.y+ad0.y), lrelu(asd0.z+ad0.z), lrelu(asd0.w+ad0.w),
                    lrelu(asd1.x+ad1.x), lrelu(asd1.y+ad1.y), lrelu(asd1.z+ad1.z), lrelu(asd1.w+ad1.w)};

    // ---- phase 1: online softmax stats ----
    float m[8], z[8];
#pragma unroll
    for (int h = 0; h < 8; h++) { m[h] = -1e30f; z[h] = 0.f; }
    if (lane == 0) {
#pragma unroll
        for (int h = 0; h < 8; h++) { m[h] = ssf[h]; z[h] = 1.f; }
    }
    for (int idx = beg + lane; idx < end; idx += 32) {
        int s = g_csrc[idx];
        float4 v0 = ((const float4*)(g_as + (size_t)s * NHD))[0];
        float4 v1 = ((const float4*)(g_as + (size_t)s * NHD))[1];
        float sc[8] = {lrelu(v0.x+adh[0]), lrelu(v0.y+adh[1]), lrelu(v0.z+adh[2]), lrelu(v0.w+adh[3]),
                       lrelu(v1.x+adh[4]), lrelu(v1.y+adh[5]), lrelu(v1.z+adh[6]), lrelu(v1.w+adh[7])};
#pragma unroll
        for (int h = 0; h < 8; h++) {
            float mn = fmaxf(m[h], sc[h]);
            z[h] = z[h] * __expf(m[h] - mn) + __expf(sc[h] - mn);
            m[h] = mn;
        }
    }
#pragma unroll
    for (int o = 16; o > 0; o >>= 1) {
#pragma unroll
        for (int h = 0; h < 8; h++) {
            float mo = __shfl_xor_sync(0xffffffffu, m[h], o);
            float zo = __shfl_xor_sync(0xffffffffu, z[h], o);
            float mn = fmaxf(m[h], mo);
            z[h] = z[h] * __expf(m[h] - mn) + zo * __expf(mo - mn);
            m[h] = mn;
        }
    }
    float zi[8];
#pragma unroll
    for (int h = 0; h < 8; h++) zi[h] = 1.0f / z[h];

    int hmy = lane >> 2;
    float m_l = 0.f, zi_l = 0.f, ad_l = 0.f;
#pragma unroll
    for (int h = 0; h < 8; h++) {
        if (lane == h) { m_l = m[h]; zi_l = zi[h]; ad_l = adh[h]; }
    }

    // ---- phase 2: weighted aggregation ----
    float p_self = 0.f;
#pragma unroll
    for (int h = 0; h < 8; h++) if (hmy == h) p_self = __expf(ssf[h] - m[h]) * zi[h];
    float2 hv = ((const float2*)(hg + (size_t)d * FD))[lane];
    float2 acc = make_float2(p_self * hv.x, p_self * hv.y);

    for (int base = beg; base < end; base += 32) {
        int n = min(32, end - base);
        int s_l = (lane < n) ? g_csrc[base + lane] : 0;
        for (int j = 0; j < n; j++) {
            int s = __shfl_sync(0xffffffffu, s_l, j);
            float p = 0.f;
            if (lane < 8) {
                float asv = g_as[(size_t)s * NHD + lane];
                p = __expf(lrelu(asv + ad_l) - m_l) * zi_l;
            }
            float pmy = __shfl_sync(0xffffffffu, p, hmy);
            float2 v = ((const float2*)(hg + (size_t)s * FD))[lane];
            acc.x += pmy * v.x; acc.y += pmy * v.y;
        }
    }
    float2 bb = ((const float2*)bg)[lane];
    float ox = fmaxf(acc.x + bb.x, 0.f);
    float oy = fmaxf(acc.y + bb.y, 0.f);
    ((float2*)(out + (size_t)d * FD))[lane] = make_float2(ox, oy);
}

// ---------------- driver ----------------
extern "C" void kernel_launch(void* const* d_in, const int* in_sizes, int n_in,
                              void* d_out, int out_size) {
    const float* x    = (const float*)d_in[0];
    const int*   ei   = (const int*)d_in[1];
    const float* W0   = (const float*)d_in[2];
    const float* b0   = (const float*)d_in[3];
    const float* Wg   = (const float*)d_in[4];
    const float* Asrc = (const float*)d_in[5];
    const float* Adst = (const float*)d_in[6];
    const float* bg   = (const float*)d_in[7];
    const float* W2   = (const float*)d_in[8];
    const float* b2   = (const float*)d_in[9];
    const float* W3   = (const float*)d_in[10];
    const float* b3   = (const float*)d_in[11];
    const int* src = ei;
    const int* dst = ei + EE;

    float* t;   cudaGetSymbolAddress((void**)&t,   g_t);
    float* acc; cudaGetSymbolAddress((void**)&acc, g_acc);
    float* outp = (float*)d_out;

    const int T = 256;
    const int gN    = CDIV(NN, T);
    const int gE    = CDIV(EE, T);
    const int gGemm = CDIV(NN, 128);
    const int gWarp = CDIV(NN * 32, T);

    // ---- CSR build ----
    k_deg_zero<<<gN, T>>>();
    k_deg<<<gE, T>>>(dst);
    k_dinv<<<gN, T>>>();
    k_scan1<<<NB, 256>>>();
    k_scan2<<<1, 512>>>();
    k_scan3<<<gN, T>>>();
    k_scatter<<<gE, T>>>(src, dst);

    // ---- layer 0: GCN(128->64) + relu ----
    k_gemm<128, 1><<<gGemm, 256>>>(x, W0, t);
    k_gcn_gather<<<gWarp, T>>>(t, acc, b0, 1);

    // ---- layer 1: GAT(64 -> 8x8 concat) + relu ----
    k_gemm<64, 0><<<gGemm, 256>>>(acc, Wg, t);
    k_alphas<<<gN, T>>>(t, Asrc, Adst);
    k_gat<<<gWarp, T>>>(t, acc, bg);

    // ---- layer 2: GCN(64->64) + relu ----
    k_gemm<64, 1><<<gGemm, 256>>>(acc, W2, t);
    k_gcn_gather<<<gWarp, T>>>(t, acc, b2, 1);

    // ---- layer 3: GCN(64->64) into d_out, no relu ----
    k_gemm<64, 1><<<gGemm, 256>>>(acc, W3, t);
    k_gcn_gather<<<gWarp, T>>>(t, outp, b3, 0);
}

// round 5
// speedup vs baseline: 2.6263x; 1.2264x over previous
#include <cuda_runtime.h>
#include <cuda_fp16.h>

#define NN 100000
#define EE 1600000
#define FD 64
#define NHD 8
#define NB  391               // CDIV(NN,256) scan blocks
#define CDIV(a,b) (((a)+(b)-1)/(b))

// ---------------- scratch ----------------
static __device__ __align__(16) float  g_dinv[NN];
static __device__ __align__(16) __half g_t  [NN*FD];   // fp16 message tensor
static __device__ __align__(16) float  g_acc[NN*FD];   // fp32 layer output (GEMM input)
static __device__ __align__(16) float  g_as [NN*NHD];
static __device__ __align__(16) float  g_ad [NN*NHD];
static __device__ int g_deg[NN];
static __device__ int g_rowptr[NN+1];
static __device__ int g_cursor[NN];
static __device__ int g_csrc[EE];
static __device__ int g_bsum[512];

__device__ __forceinline__ float lrelu(float x) { return x > 0.f ? x : 0.2f * x; }

// ---------------- CSR build ----------------
__global__ void k_deg_zero() {
    int i = blockIdx.x * blockDim.x + threadIdx.x;
    if (i < NN) g_deg[i] = 0;
}
__global__ void k_deg(const int* __restrict__ dst) {
    int e = blockIdx.x * blockDim.x + threadIdx.x;
    if (e < EE) atomicAdd(&g_deg[dst[e]], 1);
}
// scan over degrees; also computes dinv = rsqrt(deg+1)
__global__ void __launch_bounds__(256) k_scan1() {
    int i = blockIdx.x * 256 + threadIdx.x;
    int v = (i < NN) ? g_deg[i] : 0;
    if (i < NN) g_dinv[i] = rsqrtf((float)(v + 1));
    int lane = threadIdx.x & 31, wid = threadIdx.x >> 5;
    int x = v;
#pragma unroll
    for (int o = 1; o < 32; o <<= 1) { int y = __shfl_up_sync(~0u, x, o); if (lane >= o) x += y; }
    __shared__ int ws[8];
    if (lane == 31) ws[wid] = x;
    __syncthreads();
    if (wid == 0) {
        int t = (lane < 8) ? ws[lane] : 0;
#pragma unroll
        for (int o = 1; o < 8; o <<= 1) { int y = __shfl_up_sync(~0u, t, o); if (lane >= o) t += y; }
        if (lane < 8) ws[lane] = t;
    }
    __syncthreads();
    int base = wid > 0 ? ws[wid - 1] : 0;
    int incl = x + base;
    if (i < NN) g_rowptr[i] = incl - v;
    if (threadIdx.x == 255) g_bsum[blockIdx.x] = incl;
}
__global__ void __launch_bounds__(512) k_scan2() {
    int i = threadIdx.x;
    int v = (i < NB) ? g_bsum[i] : 0;
    int lane = i & 31, wid = i >> 5;
    int x = v;
#pragma unroll
    for (int o = 1; o < 32; o <<= 1) { int y = __shfl_up_sync(~0u, x, o); if (lane >= o) x += y; }
    __shared__ int ws[16];
    if (lane == 31) ws[wid] = x;
    __syncthreads();
    if (wid == 0) {
        int t = (lane < 16) ? ws[lane] : 0;
#pragma unroll
        for (int o = 1; o < 16; o <<= 1) { int y = __shfl_up_sync(~0u, t, o); if (lane >= o) t += y; }
        if (lane < 16) ws[lane] = t;
    }
    __syncthreads();
    int base = wid > 0 ? ws[wid - 1] : 0;
    if (i < NB) g_bsum[i] = x + base - v;   // exclusive
}
__global__ void k_scan3() {
    int i = blockIdx.x * blockDim.x + threadIdx.x;
    if (i < NN) {
        int r = g_rowptr[i] + g_bsum[i >> 8];
        g_rowptr[i] = r;
        g_cursor[i] = r;
    }
    if (i == 0) g_rowptr[NN] = EE;
}
__global__ void k_scatter(const int* __restrict__ src, const int* __restrict__ dst) {
    int e = blockIdx.x * blockDim.x + threadIdx.x;
    if (e >= EE) return;
    int pos = atomicAdd(&g_cursor[dst[e]], 1);
    g_csrc[pos] = src[e];
}

// ---------------- register-tiled GEMM: [NN,K] x [K,64] -> [NN,64] fp16 out ----------------
// BM=128, BN=64, BK=16, 256 threads. Thread (tx,ty): rows ty*8..+7, cols tx*4..+3.
template<int K, int SCALE>
__global__ void __launch_bounds__(256) k_gemm(const float* __restrict__ A,
                                              const float* __restrict__ W,
                                              __half* __restrict__ O) {
    constexpr int NKB = K / 16;
    __shared__ float Ws[K * 64];
    __shared__ float As[2][16 * 128];

    const int tid = threadIdx.x;
    const int tx = tid & 15, ty = tid >> 4;
    const int lr = tid >> 2, lk = tid & 3;
    const int row_blk = blockIdx.x * 128;

    {
        const float4* W4 = (const float4*)W;
        float4* Ws4 = (float4*)Ws;
#pragma unroll
        for (int i = tid; i < K * 16; i += 256) Ws4[i] = W4[i];
    }

    const float4* A4 = (const float4*)A;
    float4 rg[2];
#pragma unroll
    for (int h = 0; h < 2; h++) {
        int grow = row_blk + lr + h * 64;
        rg[h] = (grow < NN) ? A4[(size_t)grow * (K / 4) + lk]
                            : make_float4(0.f, 0.f, 0.f, 0.f);
    }
#pragma unroll
    for (int h = 0; h < 2; h++) {
        int r = lr + h * 64;
        As[0][(lk * 4 + 0) * 128 + r] = rg[h].x;
        As[0][(lk * 4 + 1) * 128 + r] = rg[h].y;
        As[0][(lk * 4 + 2) * 128 + r] = rg[h].z;
        As[0][(lk * 4 + 3) * 128 + r] = rg[h].w;
    }
    __syncthreads();

    float acc[8][4];
#pragma unroll
    for (int i = 0; i < 8; i++)
#pragma unroll
        for (int j = 0; j < 4; j++) acc[i][j] = 0.f;

    for (int kb = 0; kb < NKB; kb++) {
        int b = kb & 1;
        if (kb + 1 < NKB) {
#pragma unroll
            for (int h = 0; h < 2; h++) {
                int grow = row_blk + lr + h * 64;
                rg[h] = (grow < NN) ? A4[(size_t)grow * (K / 4) + (kb + 1) * 4 + lk]
                                    : make_float4(0.f, 0.f, 0.f, 0.f);
            }
        }
#pragma unroll
        for (int k = 0; k < 16; k++) {
            float4 w = *(const float4*)&Ws[(kb * 16 + k) * 64 + tx * 4];
            float4 a0 = *(const float4*)&As[b][k * 128 + ty * 8];
            float4 a1 = *(const float4*)&As[b][k * 128 + ty * 8 + 4];
            float av[8] = {a0.x, a0.y, a0.z, a0.w, a1.x, a1.y, a1.z, a1.w};
#pragma unroll
            for (int i = 0; i < 8; i++) {
                acc[i][0] += av[i] * w.x;
                acc[i][1] += av[i] * w.y;
                acc[i][2] += av[i] * w.z;
                acc[i][3] += av[i] * w.w;
            }
        }
        if (kb + 1 < NKB) {
            int nb = (kb + 1) & 1;
#pragma unroll
            for (int h = 0; h < 2; h++) {
                int r = lr + h * 64;
                As[nb][(lk * 4 + 0) * 128 + r] = rg[h].x;
                As[nb][(lk * 4 + 1) * 128 + r] = rg[h].y;
                As[nb][(lk * 4 + 2) * 128 + r] = rg[h].z;
                As[nb][(lk * 4 + 3) * 128 + r] = rg[h].w;
            }
            __syncthreads();
        }
    }

#pragma unroll
    for (int i = 0; i < 8; i++) {
        int row = row_blk + ty * 8 + i;
        if (row < NN) {
            float sc = SCALE ? g_dinv[row] : 1.0f;
            __half2 h0 = __float22half2_rn(make_float2(acc[i][0] * sc, acc[i][1] * sc));
            __half2 h1 = __float22half2_rn(make_float2(acc[i][2] * sc, acc[i][3] * sc));
            uint2 pk;
            pk.x = *(unsigned*)&h0;
            pk.y = *(unsigned*)&h1;
            ((uint2*)(O + (size_t)row * FD))[tx] = pk;
        }
    }
}

// ---------------- GCN gather (warp per node, fp16 messages) ----------------
__global__ void __launch_bounds__(256) k_gcn_gather(const __half* __restrict__ ts,
                                                    float* __restrict__ out,
                                                    const float* __restrict__ b,
                                                    int do_relu) {
    int warp = (blockIdx.x * blockDim.x + threadIdx.x) >> 5;
    int lane = threadIdx.x & 31;
    if (warp >= NN) return;
    int d = warp;
    int beg = g_rowptr[d], end = g_rowptr[d + 1];
    float2 acc = __half22float2(((const __half2*)(ts + (size_t)d * FD))[lane]);  // self
    for (int base = beg; base < end; base += 32) {
        int n = min(32, end - base);
        int s_l = (lane < n) ? g_csrc[base + lane] : 0;
        for (int j = 0; j < n; j++) {
            int s = __shfl_sync(0xffffffffu, s_l, j);
            float2 v = __half22float2(((const __half2*)(ts + (size_t)s * FD))[lane]);
            acc.x += v.x; acc.y += v.y;
        }
    }
    float nv = g_dinv[d];
    float2 bb = ((const float2*)b)[lane];
    float ox = acc.x * nv + bb.x, oy = acc.y * nv + bb.y;
    if (do_relu) { ox = fmaxf(ox, 0.f); oy = fmaxf(oy, 0.f); }
    ((float2*)(out + (size_t)d * FD))[lane] = make_float2(ox, oy);
}

// ---------------- GAT ----------------
__global__ void k_alphas(const __half* __restrict__ hg, const float* __restrict__ Asrc,
                         const float* __restrict__ Adst) {
    int i = blockIdx.x * blockDim.x + threadIdx.x;
    if (i >= NN) return;
    const __half2* h2 = (const __half2*)(hg + (size_t)i * FD);
#pragma unroll
    for (int h = 0; h < NHD; h++) {
        float as = 0.f, ad = 0.f;
#pragma unroll
        for (int c = 0; c < 4; c++) {
            float2 v = __half22float2(h2[h * 4 + c]);
            float2 s = ((const float2*)Asrc)[h * 4 + c];
            float2 t = ((const float2*)Adst)[h * 4 + c];
            as += v.x * s.x + v.y * s.y;
            ad += v.x * t.x + v.y * t.y;
        }
        g_as[i * NHD + h] = as;
        g_ad[i * NHD + h] = ad;
    }
}

// Fused GAT: max pass (no exp) + single-exp aggregation with deferred normalization.
__global__ void __launch_bounds__(256) k_gat(const __half* __restrict__ hg,
                                             float* __restrict__ out,
                                             const float* __restrict__ bg) {
    int warp = (blockIdx.x * blockDim.x + threadIdx.x) >> 5;
    int lane = threadIdx.x & 31;
    if (warp >= NN) return;
    int d = warp;
    int beg = g_rowptr[d], end = g_rowptr[d + 1];

    float4 ad0 = ((const float4*)(g_ad + (size_t)d * NHD))[0];
    float4 ad1 = ((const float4*)(g_ad + (size_t)d * NHD))[1];
    float4 asd0 = ((const float4*)(g_as + (size_t)d * NHD))[0];
    float4 asd1 = ((const float4*)(g_as + (size_t)d * NHD))[1];
    float adh[8] = {ad0.x, ad0.y, ad0.z, ad0.w, ad1.x, ad1.y, ad1.z, ad1.w};
    float ssf[8] = {lrelu(asd0.x+ad0.x), lrelu(asd0.y+ad0.y), lrelu(asd0.z+ad0.z), lrelu(asd0.w+ad0.w),
                    lrelu(asd1.x+ad1.x), lrelu(asd1.y+ad1.y), lrelu(asd1.z+ad1.z), lrelu(asd1.w+ad1.w)};

    // ---- phase 1: segment max only (no exp) ----
    float m[8];
#pragma unroll
    for (int h = 0; h < 8; h++) m[h] = ssf[h];   // self-loop score (all lanes)
    for (int idx = beg + lane; idx < end; idx += 32) {
        int s = g_csrc[idx];
        float4 v0 = ((const float4*)(g_as + (size_t)s * NHD))[0];
        float4 v1 = ((const float4*)(g_as + (size_t)s * NHD))[1];
        m[0] = fmaxf(m[0], lrelu(v0.x + adh[0]));
        m[1] = fmaxf(m[1], lrelu(v0.y + adh[1]));
        m[2] = fmaxf(m[2], lrelu(v0.z + adh[2]));
        m[3] = fmaxf(m[3], lrelu(v0.w + adh[3]));
        m[4] = fmaxf(m[4], lrelu(v1.x + adh[4]));
        m[5] = fmaxf(m[5], lrelu(v1.y + adh[5]));
        m[6] = fmaxf(m[6], lrelu(v1.z + adh[6]));
        m[7] = fmaxf(m[7], lrelu(v1.w + adh[7]));
    }
#pragma unroll
    for (int o = 16; o > 0; o >>= 1) {
#pragma unroll
        for (int h = 0; h < 8; h++)
            m[h] = fmaxf(m[h], __shfl_xor_sync(0xffffffffu, m[h], o));
    }

    // per-lane scalars for the scoring lanes (lane h scores head h)
    float m_l = 0.f, ad_l = 0.f, ssf_l = 0.f;
#pragma unroll
    for (int h = 0; h < 8; h++) {
        if (lane == h) { m_l = m[h]; ad_l = adh[h]; ssf_l = ssf[h]; }
    }
    int hmy = lane >> 2;   // head owning this lane's feature pair

    // ---- phase 2: unnormalized weighted aggregation; z accumulated by scoring lanes ----
    float z_l = (lane < 8) ? __expf(ssf_l - m_l) : 0.f;   // self term of z
    float pself_l = z_l;
    float pself_my = __shfl_sync(0xffffffffu, pself_l, hmy);
    float2 hv = __half22float2(((const __half2*)(hg + (size_t)d * FD))[lane]);
    float2 acc = make_float2(pself_my * hv.x, pself_my * hv.y);

    for (int base = beg; base < end; base += 32) {
        int n = min(32, end - base);
        int s_l = (lane < n) ? g_csrc[base + lane] : 0;
        for (int j = 0; j < n; j++) {
            int s = __shfl_sync(0xffffffffu, s_l, j);
            float p = 0.f;
            if (lane < 8) {
                float asv = g_as[(size_t)s * NHD + lane];
                p = __expf(lrelu(asv + ad_l) - m_l);
                z_l += p;
            }
            float pmy = __shfl_sync(0xffffffffu, p, hmy);
            float2 v = __half22float2(((const __half2*)(hg + (size_t)s * FD))[lane]);
            acc.x += pmy * v.x; acc.y += pmy * v.y;
        }
    }
    float zi_l = (lane < 8) ? (1.0f / z_l) : 0.f;
    float zi_my = __shfl_sync(0xffffffffu, zi_l, hmy);

    float2 bb = ((const float2*)bg)[lane];
    float ox = fmaxf(acc.x * zi_my + bb.x, 0.f);
    float oy = fmaxf(acc.y * zi_my + bb.y, 0.f);
    ((float2*)(out + (size_t)d * FD))[lane] = make_float2(ox, oy);
}

// ---------------- driver ----------------
extern "C" void kernel_launch(void* const* d_in, const int* in_sizes, int n_in,
                              void* d_out, int out_size) {
    const float* x    = (const float*)d_in[0];
    const int*   ei   = (const int*)d_in[1];
    const float* W0   = (const float*)d_in[2];
    const float* b0   = (const float*)d_in[3];
    const float* Wg   = (const float*)d_in[4];
    const float* Asrc = (const float*)d_in[5];
    const float* Adst = (const float*)d_in[6];
    const float* bg   = (const float*)d_in[7];
    const float* W2   = (const float*)d_in[8];
    const float* b2   = (const float*)d_in[9];
    const float* W3   = (const float*)d_in[10];
    const float* b3   = (const float*)d_in[11];
    const int* src = ei;
    const int* dst = ei + EE;

    __half* t;  cudaGetSymbolAddress((void**)&t,   g_t);
    float* acc; cudaGetSymbolAddress((void**)&acc, g_acc);
    float* outp = (float*)d_out;

    const int T = 256;
    const int gN    = CDIV(NN, T);
    const int gE    = CDIV(EE, T);
    const int gGemm = CDIV(NN, 128);
    const int gWarp = CDIV(NN * 32, T);

    // ---- CSR build ----
    k_deg_zero<<<gN, T>>>();
    k_deg<<<gE, T>>>(dst);
    k_scan1<<<NB, 256>>>();
    k_scan2<<<1, 512>>>();
    k_scan3<<<gN, T>>>();
    k_scatter<<<gE, T>>>(src, dst);

    // ---- layer 0: GCN(128->64) + relu ----
    k_gemm<128, 1><<<gGemm, 256>>>(x, W0, t);
    k_gcn_gather<<<gWarp, T>>>(t, acc, b0, 1);

    // ---- layer 1: GAT(64 -> 8x8 concat) + relu ----
    k_gemm<64, 0><<<gGemm, 256>>>(acc, Wg, t);
    k_alphas<<<gN, T>>>(t, Asrc, Adst);
    k_gat<<<gWarp, T>>>(t, acc, bg);

    // ---- layer 2: GCN(64->64) + relu ----
    k_gemm<64, 1><<<gGemm, 256>>>(acc, W2, t);
    k_gcn_gather<<<gWarp, T>>>(t, acc, b2, 1);

    // ---- layer 3: GCN(64->64) into d_out, no relu ----
    k_gemm<64, 1><<<gGemm, 256>>>(acc, W3, t);
    k_gcn_gather<<<gWarp, T>>>(t, outp, b3, 0);
}

// round 9
// speedup vs baseline: 3.0131x; 1.1473x over previous
#include <cuda_runtime.h>
#include <cuda_fp16.h>
#include <cstdint>

#define NN 100000
#define EE 1600000
#define FD 64
#define NHD 8
#define NB  391               // CDIV(NN,256) scan blocks
#define CDIV(a,b) (((a)+(b)-1)/(b))

// ---------------- scratch ----------------
static __device__ __align__(16) float  g_dinv[NN];
static __device__ __align__(16) __half g_t  [NN*FD];     // GEMM output (messages)
static __device__ __align__(16) __half g_h  [NN*FD];     // layer activations (fp16)
static __device__ __align__(16) __half g_w16[20480];     // W0(8192) Wg(4096) W2(4096) W3(4096)
static __device__ __align__(16) float  g_as [NN*NHD];
static __device__ __align__(16) float  g_ad [NN*NHD];
static __device__ int g_deg[NN];
static __device__ int g_rowptr[NN+1];
static __device__ int g_cursor[NN];
static __device__ int g_csrc[EE];
static __device__ int g_bsum[512];

__device__ __forceinline__ float lrelu(float x) { return x > 0.f ? x : 0.2f * x; }
__device__ __forceinline__ uint32_t qpack(float a, float b) {
    __half2 h = __float22half2_rn(make_float2(a, b));
    return *(uint32_t*)&h;
}

// ---------------- CSR build ----------------
__global__ void k_deg_zero() {
    int i = blockIdx.x * blockDim.x + threadIdx.x;
    if (i < NN) g_deg[i] = 0;
}
__global__ void k_deg(const int* __restrict__ dst) {
    int e = blockIdx.x * blockDim.x + threadIdx.x;
    if (e < EE) atomicAdd(&g_deg[dst[e]], 1);
}
__global__ void __launch_bounds__(256) k_scan1() {
    int i = blockIdx.x * 256 + threadIdx.x;
    int v = (i < NN) ? g_deg[i] : 0;
    if (i < NN) g_dinv[i] = rsqrtf((float)(v + 1));
    int lane = threadIdx.x & 31, wid = threadIdx.x >> 5;
    int x = v;
#pragma unroll
    for (int o = 1; o < 32; o <<= 1) { int y = __shfl_up_sync(~0u, x, o); if (lane >= o) x += y; }
    __shared__ int ws[8];
    if (lane == 31) ws[wid] = x;
    __syncthreads();
    if (wid == 0) {
        int t = (lane < 8) ? ws[lane] : 0;
#pragma unroll
        for (int o = 1; o < 8; o <<= 1) { int y = __shfl_up_sync(~0u, t, o); if (lane >= o) t += y; }
        if (lane < 8) ws[lane] = t;
    }
    __syncthreads();
    int base = wid > 0 ? ws[wid - 1] : 0;
    int incl = x + base;
    if (i < NN) g_rowptr[i] = incl - v;
    if (threadIdx.x == 255) g_bsum[blockIdx.x] = incl;
}
__global__ void __launch_bounds__(512) k_scan2() {
    int i = threadIdx.x;
    int v = (i < NB) ? g_bsum[i] : 0;
    int lane = i & 31, wid = i >> 5;
    int x = v;
#pragma unroll
    for (int o = 1; o < 32; o <<= 1) { int y = __shfl_up_sync(~0u, x, o); if (lane >= o) x += y; }
    __shared__ int ws[16];
    if (lane == 31) ws[wid] = x;
    __syncthreads();
    if (wid == 0) {
        int t = (lane < 16) ? ws[lane] : 0;
#pragma unroll
        for (int o = 1; o < 16; o <<= 1) { int y = __shfl_up_sync(~0u, t, o); if (lane >= o) t += y; }
        if (lane < 16) ws[lane] = t;
    }
    __syncthreads();
    int base = wid > 0 ? ws[wid - 1] : 0;
    if (i < NB) g_bsum[i] = x + base - v;
}
__global__ void k_scan3() {
    int i = blockIdx.x * blockDim.x + threadIdx.x;
    if (i < NN) {
        int r = g_rowptr[i] + g_bsum[i >> 8];
        g_rowptr[i] = r;
        g_cursor[i] = r;
    }
    if (i == 0) g_rowptr[NN] = EE;
}
__global__ void k_scatter(const int* __restrict__ src, const int* __restrict__ dst) {
    int e = blockIdx.x * blockDim.x + threadIdx.x;
    if (e >= EE) return;
    int pos = atomicAdd(&g_cursor[dst[e]], 1);
    g_csrc[pos] = src[e];
}

// ---------------- weight conversion to fp16 ----------------
__global__ void k_w2h(const float* __restrict__ W0, const float* __restrict__ Wg,
                      const float* __restrict__ W2, const float* __restrict__ W3) {
    int i = blockIdx.x * blockDim.x + threadIdx.x;
    if (i < 8192) g_w16[i] = __float2half(W0[i]);
    if (i < 4096) {
        g_w16[8192  + i] = __float2half(Wg[i]);
        g_w16[12288 + i] = __float2half(W2[i]);
        g_w16[16384 + i] = __float2half(W3[i]);
    }
}

// ---------------- tensor-core GEMM: [NN,K]x[K,64] -> fp16 [NN,64] ----------------
__device__ __forceinline__ void ldsm4(uint32_t a, uint32_t& r0, uint32_t& r1,
                                      uint32_t& r2, uint32_t& r3) {
    asm volatile("ldmatrix.sync.aligned.m8n8.x4.shared.b16 {%0,%1,%2,%3}, [%4];"
                 : "=r"(r0), "=r"(r1), "=r"(r2), "=r"(r3) : "r"(a));
}
__device__ __forceinline__ void ldsm4t(uint32_t a, uint32_t& r0, uint32_t& r1,
                                       uint32_t& r2, uint32_t& r3) {
    asm volatile("ldmatrix.sync.aligned.m8n8.x4.trans.shared.b16 {%0,%1,%2,%3}, [%4];"
                 : "=r"(r0), "=r"(r1), "=r"(r2), "=r"(r3) : "r"(a));
}
__device__ __forceinline__ void mma16816(float* c, const uint32_t* a, uint32_t b0, uint32_t b1) {
    asm volatile("mma.sync.aligned.m16n8k16.row.col.f32.f16.f16.f32 "
                 "{%0,%1,%2,%3}, {%4,%5,%6,%7}, {%8,%9}, {%0,%1,%2,%3};"
                 : "+f"(c[0]), "+f"(c[1]), "+f"(c[2]), "+f"(c[3])
                 : "r"(a[0]), "r"(a[1]), "r"(a[2]), "r"(a[3]), "r"(b0), "r"(b1));
}

// AF32: A is fp32 (converted during staging); else fp16. SCALE: multiply rows by dinv.
template<int K, int SCALE, int AF32>
__global__ void __launch_bounds__(128) k_gemm_mma(const void* __restrict__ Ain,
                                                  const __half* __restrict__ W16,
                                                  __half* __restrict__ O) {
    constexpr int NKB = K / 16;
    __shared__ __align__(16) __half Ws[K * 64];
    __shared__ __align__(16) __half As[2][128 * 24];   // 48B row stride (bank-safe)

    const int tid = threadIdx.x;
    const int lane = tid & 31, w = tid >> 5;
    const int row_blk = blockIdx.x * 128;

    // stage W into smem, XOR-swizzled 16B units: unit(kk,n16) -> kk*8 + (n16^(kk&7))
    for (int u = tid; u < K * 8; u += 128) {
        int kk = u >> 3, n16 = u & 7;
        ((uint4*)Ws)[(kk << 3) | (n16 ^ (kk & 7))] = ((const uint4*)W16)[u];
    }

    auto load_regs = [&](int kb, uint4* r) {
        int grow = row_blk + tid;
        if (AF32) {
            const float4* s = (const float4*)((const float*)Ain + (size_t)grow * K + kb * 16);
            float4 f0, f1, f2, f3;
            if (grow < NN) { f0 = s[0]; f1 = s[1]; f2 = s[2]; f3 = s[3]; }
            else { f0 = f1 = f2 = f3 = make_float4(0.f, 0.f, 0.f, 0.f); }
            r[0] = make_uint4(qpack(f0.x, f0.y), qpack(f0.z, f0.w),
                              qpack(f1.x, f1.y), qpack(f1.z, f1.w));
            r[1] = make_uint4(qpack(f2.x, f2.y), qpack(f2.z, f2.w),
                              qpack(f3.x, f3.y), qpack(f3.z, f3.w));
        } else {
            const uint4* s = (const uint4*)((const __half*)Ain + (size_t)grow * K + kb * 16);
            if (grow < NN) { r[0] = s[0]; r[1] = s[1]; }
            else { r[0] = r[1] = make_uint4(0u, 0u, 0u, 0u); }
        }
    };
    auto store_regs = [&](int buf, const uint4* r) {
        uint4* d = (uint4*)(As[buf] + tid * 24);
        d[0] = r[0]; d[1] = r[1];
    };

    uint4 rg[2];
    load_regs(0, rg);
    store_regs(0, rg);
    __syncthreads();

    float acc[2][8][4];
#pragma unroll
    for (int mi = 0; mi < 2; mi++)
#pragma unroll
        for (int ni = 0; ni < 8; ni++)
#pragma unroll
            for (int q = 0; q < 4; q++) acc[mi][ni][q] = 0.f;

    uint32_t as_u = (uint32_t)__cvta_generic_to_shared(As);
    uint32_t ws_u = (uint32_t)__cvta_generic_to_shared(Ws);

    for (int kb = 0; kb < NKB; kb++) {
        if (kb + 1 < NKB) load_regs(kb + 1, rg);
        int b = kb & 1;
        uint32_t af[2][4];
#pragma unroll
        for (int mi = 0; mi < 2; mi++) {
            uint32_t aa = as_u + b * 6144
                        + (w * 32 + mi * 16 + (lane & 15)) * 48 + ((lane >> 4) << 4);
            ldsm4(aa, af[mi][0], af[mi][1], af[mi][2], af[mi][3]);
        }
        uint32_t bf[4][4];
        int sub = lane >> 3;
        int krow = kb * 16 + ((sub & 1) << 3) + (lane & 7);
#pragma unroll
        for (int g = 0; g < 4; g++) {
            int ucol = g * 2 + (sub >> 1);
            uint32_t ba = ws_u + ((uint32_t)((krow << 3) | (ucol ^ (krow & 7))) << 4);
            ldsm4t(ba, bf[g][0], bf[g][1], bf[g][2], bf[g][3]);
        }
#pragma unroll
        for (int mi = 0; mi < 2; mi++)
#pragma unroll
            for (int ni = 0; ni < 8; ni++) {
                int g = ni >> 1, o = (ni & 1) << 1;
                mma16816(acc[mi][ni], af[mi], bf[g][o], bf[g][o + 1]);
            }
        if (kb + 1 < NKB) {
            store_regs((kb + 1) & 1, rg);
            __syncthreads();
        }
    }

    // epilogue: C frag (c0,c1)=row lane/4, cols 2*(lane%4)+{0,1}; (c2,c3)=row+8
#pragma unroll
    for (int mi = 0; mi < 2; mi++) {
        int r0 = row_blk + w * 32 + mi * 16 + (lane >> 2);
        int r1 = r0 + 8;
        float s0 = 1.f, s1 = 1.f;
        if (SCALE) {
            if (r0 < NN) s0 = g_dinv[r0];
            if (r1 < NN) s1 = g_dinv[r1];
        }
#pragma unroll
        for (int ni = 0; ni < 8; ni++) {
            int c = ni * 8 + (lane & 3) * 2;
            if (r0 < NN) {
                __half2 h = __float22half2_rn(make_float2(acc[mi][ni][0] * s0, acc[mi][ni][1] * s0));
                *(__half2*)(O + (size_t)r0 * FD + c) = h;
            }
            if (r1 < NN) {
                __half2 h = __float22half2_rn(make_float2(acc[mi][ni][2] * s1, acc[mi][ni][3] * s1));
                *(__half2*)(O + (size_t)r1 * FD + c) = h;
            }
        }
    }
}

// ---------------- GCN gather (warp per node, fp16 messages) ----------------
// HOUT=1: write fp16 (activation buffer); HOUT=0: write fp32 (final output)
template<int HOUT>
__global__ void __launch_bounds__(256) k_gcn_gather(const __half* __restrict__ ts,
                                                    void* __restrict__ outv,
                                                    const float* __restrict__ b,
                                                    int do_relu) {
    int warp = (blockIdx.x * blockDim.x + threadIdx.x) >> 5;
    int lane = threadIdx.x & 31;
    if (warp >= NN) return;
    int d = warp;
    int beg = g_rowptr[d], end = g_rowptr[d + 1];
    float2 acc = __half22float2(((const __half2*)(ts + (size_t)d * FD))[lane]);
    for (int base = beg; base < end; base += 32) {
        int n = min(32, end - base);
        int s_l = (lane < n) ? g_csrc[base + lane] : 0;
        for (int j = 0; j < n; j++) {
            int s = __shfl_sync(0xffffffffu, s_l, j);
            float2 v = __half22float2(((const __half2*)(ts + (size_t)s * FD))[lane]);
            acc.x += v.x; acc.y += v.y;
        }
    }
    float nv = g_dinv[d];
    float2 bb = ((const float2*)b)[lane];
    float ox = acc.x * nv + bb.x, oy = acc.y * nv + bb.y;
    if (do_relu) { ox = fmaxf(ox, 0.f); oy = fmaxf(oy, 0.f); }
    if (HOUT) {
        ((__half2*)((__half*)outv + (size_t)d * FD))[lane] = __float22half2_rn(make_float2(ox, oy));
    } else {
        ((float2*)((float*)outv + (size_t)d * FD))[lane] = make_float2(ox, oy);
    }
}

// ---------------- GAT ----------------
__global__ void k_alphas(const __half* __restrict__ hg, const float* __restrict__ Asrc,
                         const float* __restrict__ Adst) {
    int i = blockIdx.x * blockDim.x + threadIdx.x;
    if (i >= NN) return;
    const __half2* h2 = (const __half2*)(hg + (size_t)i * FD);
#pragma unroll
    for (int h = 0; h < NHD; h++) {
        float as = 0.f, ad = 0.f;
#pragma unroll
        for (int c = 0; c < 4; c++) {
            float2 v = __half22float2(h2[h * 4 + c]);
            float2 s = ((const float2*)Asrc)[h * 4 + c];
            float2 t = ((const float2*)Adst)[h * 4 + c];
            as += v.x * s.x + v.y * s.y;
            ad += v.x * t.x + v.y * t.y;
        }
        g_as[i * NHD + h] = as;
        g_ad[i * NHD + h] = ad;
    }
}

// Fused GAT: max pass + single-exp aggregation with deferred normalization. fp16 out.
__global__ void __launch_bounds__(256) k_gat(const __half* __restrict__ hg,
                                             __half* __restrict__ out,
                                             const float* __restrict__ bg) {
    int warp = (blockIdx.x * blockDim.x + threadIdx.x) >> 5;
    int lane = threadIdx.x & 31;
    if (warp >= NN) return;
    int d = warp;
    int beg = g_rowptr[d], end = g_rowptr[d + 1];

    float4 ad0 = ((const float4*)(g_ad + (size_t)d * NHD))[0];
    float4 ad1 = ((const float4*)(g_ad + (size_t)d * NHD))[1];
    float4 asd0 = ((const float4*)(g_as + (size_t)d * NHD))[0];
    float4 asd1 = ((const float4*)(g_as + (size_t)d * NHD))[1];
    float adh[8] = {ad0.x, ad0.y, ad0.z, ad0.w, ad1.x, ad1.y, ad1.z, ad1.w};
    float ssf[8] = {lrelu(asd0.x+ad0.x), lrelu(asd0.y+ad0.y), lrelu(asd0.z+ad0.z), lrelu(asd0.w+ad0.w),
                    lrelu(asd1.x+ad1.x), lrelu(asd1.y+ad1.y), lrelu(asd1.z+ad1.z), lrelu(asd1.w+ad1.w)};

    // phase 1: segment max only
    float m[8];
#pragma unroll
    for (int h = 0; h < 8; h++) m[h] = ssf[h];
    for (int idx = beg + lane; idx < end; idx += 32) {
        int s = g_csrc[idx];
        float4 v0 = ((const float4*)(g_as + (size_t)s * NHD))[0];
        float4 v1 = ((const float4*)(g_as + (size_t)s * NHD))[1];
        m[0] = fmaxf(m[0], lrelu(v0.x + adh[0]));
        m[1] = fmaxf(m[1], lrelu(v0.y + adh[1]));
        m[2] = fmaxf(m[2], lrelu(v0.z + adh[2]));
        m[3] = fmaxf(m[3], lrelu(v0.w + adh[3]));
        m[4] = fmaxf(m[4], lrelu(v1.x + adh[4]));
        m[5] = fmaxf(m[5], lrelu(v1.y + adh[5]));
        m[6] = fmaxf(m[6], lrelu(v1.z + adh[6]));
        m[7] = fmaxf(m[7], lrelu(v1.w + adh[7]));
    }
#pragma unroll
    for (int o = 16; o > 0; o >>= 1) {
#pragma unroll
        for (int h = 0; h < 8; h++)
            m[h] = fmaxf(m[h], __shfl_xor_sync(0xffffffffu, m[h], o));
    }

    float m_l = 0.f, ad_l = 0.f, ssf_l = 0.f;
#pragma unroll
    for (int h = 0; h < 8; h++) {
        if (lane == h) { m_l = m[h]; ad_l = adh[h]; ssf_l = ssf[h]; }
    }
    int hmy = lane >> 2;

    // phase 2: unnormalized aggregation; z accumulated by scoring lanes
    float z_l = (lane < 8) ? __expf(ssf_l - m_l) : 0.f;
    float pself_my = __shfl_sync(0xffffffffu, z_l, hmy);
    float2 hv = __half22float2(((const __half2*)(hg + (size_t)d * FD))[lane]);
    float2 acc = make_float2(pself_my * hv.x, pself_my * hv.y);

    for (int base = beg; base < end; base += 32) {
        int n = min(32, end - base);
        int s_l = (lane < n) ? g_csrc[base + lane] : 0;
        for (int j = 0; j < n; j++) {
            int s = __shfl_sync(0xffffffffu, s_l, j);
            float p = 0.f;
            if (lane < 8) {
                float asv = g_as[(size_t)s * NHD + lane];
                p = __expf(lrelu(asv + ad_l) - m_l);
                z_l += p;
            }
            float pmy = __shfl_sync(0xffffffffu, p, hmy);
            float2 v = __half22float2(((const __half2*)(hg + (size_t)s * FD))[lane]);
            acc.x += pmy * v.x; acc.y += pmy * v.y;
        }
    }
    float zi_l = (lane < 8) ? (1.0f / z_l) : 0.f;
    float zi_my = __shfl_sync(0xffffffffu, zi_l, hmy);

    float2 bb = ((const float2*)bg)[lane];
    float ox = fmaxf(acc.x * zi_my + bb.x, 0.f);
    float oy = fmaxf(acc.y * zi_my + bb.y, 0.f);
    ((__half2*)(out + (size_t)d * FD))[lane] = __float22half2_rn(make_float2(ox, oy));
}

// ---------------- driver ----------------
extern "C" void kernel_launch(void* const* d_in, const int* in_sizes, int n_in,
                              void* d_out, int out_size) {
    const float* x    = (const float*)d_in[0];
    const int*   ei   = (const int*)d_in[1];
    const float* W0   = (const float*)d_in[2];
    const float* b0   = (const float*)d_in[3];
    const float* Wg   = (const float*)d_in[4];
    const float* Asrc = (const float*)d_in[5];
    const float* Adst = (const float*)d_in[6];
    const float* bg   = (const float*)d_in[7];
    const float* W2   = (const float*)d_in[8];
    const float* b2   = (const float*)d_in[9];
    const float* W3   = (const float*)d_in[10];
    const float* b3   = (const float*)d_in[11];
    const int* src = ei;
    const int* dst = ei + EE;

    __half* t16; cudaGetSymbolAddress((void**)&t16, g_t);
    __half* h16; cudaGetSymbolAddress((void**)&h16, g_h);
    __half* w16; cudaGetSymbolAddress((void**)&w16, g_w16);
    float* outp = (float*)d_out;

    const int T = 256;
    const int gN    = CDIV(NN, T);
    const int gE    = CDIV(EE, T);
    const int gGemm = CDIV(NN, 128);
    const int gWarp = CDIV(NN * 32, T);

    // ---- weight conversion + CSR build ----
    k_w2h<<<32, 256>>>(W0, Wg, W2, W3);
    k_deg_zero<<<gN, T>>>();
    k_deg<<<gE, T>>>(dst);
    k_scan1<<<NB, 256>>>();
    k_scan2<<<1, 512>>>();
    k_scan3<<<gN, T>>>();
    k_scatter<<<gE, T>>>(src, dst);

    // ---- layer 0: GCN(128->64) + relu ----
    k_gemm_mma<128, 1, 1><<<gGemm, 128>>>(x, w16, t16);
    k_gcn_gather<1><<<gWarp, T>>>(t16, h16, b0, 1);

    // ---- layer 1: GAT(64 -> 8x8 concat) + relu ----
    k_gemm_mma<64, 0, 0><<<gGemm, 128>>>(h16, w16 + 8192, t16);
    k_alphas<<<gN, T>>>(t16, Asrc, Adst);
    k_gat<<<gWarp, T>>>(t16, h16, bg);

    // ---- layer 2: GCN(64->64) + relu ----
    k_gemm_mma<64, 1, 0><<<gGemm, 128>>>(h16, w16 + 12288, t16);
    k_gcn_gather<1><<<gWarp, T>>>(t16, h16, b2, 1);

    // ---- layer 3: GCN(64->64) into d_out, no relu ----
    k_gemm_mma<64, 1, 0><<<gGemm, 128>>>(h16, w16 + 16384, t16);
    k_gcn_gather<0><<<gWarp, T>>>(t16, outp, b3, 0);
}

// round 10
// speedup vs baseline: 3.2958x; 1.0938x over previous
#include <cuda_runtime.h>
#include <cuda_fp16.h>
#include <cstdint>

#define NN 100000
#define EE 1600000
#define FD 64
#define NHD 8
#define NB  391               // CDIV(NN,256) scan blocks
#define CDIV(a,b) (((a)+(b)-1)/(b))

// ---------------- scratch ----------------
static __device__ __align__(16) float  g_dinv[NN];
static __device__ __align__(16) __half g_t  [NN*FD];     // GEMM output (messages)
static __device__ __align__(16) __half g_h  [NN*FD];     // layer activations (fp16)
static __device__ __align__(16) __half g_w16[20480];     // W0(8192) Wg(4096) W2(4096) W3(4096)
static __device__ __align__(16) float  g_as [NN*NHD];
static __device__ __align__(16) float  g_ad [NN*NHD];
static __device__ int g_deg[NN];
static __device__ int g_rowptr[NN+1];
static __device__ int g_cursor[NN];
static __device__ int g_csrc[EE];
static __device__ int g_bsum[512];

__device__ __forceinline__ float lrelu(float x) { return x > 0.f ? x : 0.2f * x; }
__device__ __forceinline__ uint32_t qpack(float a, float b) {
    __half2 h = __float22half2_rn(make_float2(a, b));
    return *(uint32_t*)&h;
}

// ---------------- weight conversion + degree zero ----------------
__global__ void k_w2h(const float* __restrict__ W0, const float* __restrict__ Wg,
                      const float* __restrict__ W2, const float* __restrict__ W3) {
    int i = blockIdx.x * blockDim.x + threadIdx.x;
    if (i < NN) g_deg[i] = 0;
    if (i < 8192) g_w16[i] = __float2half(W0[i]);
    if (i < 4096) {
        g_w16[8192  + i] = __float2half(Wg[i]);
        g_w16[12288 + i] = __float2half(W2[i]);
        g_w16[16384 + i] = __float2half(W3[i]);
    }
}

// ---------------- CSR build ----------------
__global__ void k_deg(const int* __restrict__ dst) {
    int e = blockIdx.x * blockDim.x + threadIdx.x;
    if (e < EE) atomicAdd(&g_deg[dst[e]], 1);
}
__global__ void __launch_bounds__(256) k_scan1() {
    int i = blockIdx.x * 256 + threadIdx.x;
    int v = (i < NN) ? g_deg[i] : 0;
    if (i < NN) g_dinv[i] = rsqrtf((float)(v + 1));
    int lane = threadIdx.x & 31, wid = threadIdx.x >> 5;
    int x = v;
#pragma unroll
    for (int o = 1; o < 32; o <<= 1) { int y = __shfl_up_sync(~0u, x, o); if (lane >= o) x += y; }
    __shared__ int ws[8];
    if (lane == 31) ws[wid] = x;
    __syncthreads();
    if (wid == 0) {
        int t = (lane < 8) ? ws[lane] : 0;
#pragma unroll
        for (int o = 1; o < 8; o <<= 1) { int y = __shfl_up_sync(~0u, t, o); if (lane >= o) t += y; }
        if (lane < 8) ws[lane] = t;
    }
    __syncthreads();
    int base = wid > 0 ? ws[wid - 1] : 0;
    int incl = x + base;
    if (i < NN) g_rowptr[i] = incl - v;
    if (threadIdx.x == 255) g_bsum[blockIdx.x] = incl;
}
__global__ void __launch_bounds__(512) k_scan2() {
    int i = threadIdx.x;
    int v = (i < NB) ? g_bsum[i] : 0;
    int lane = i & 31, wid = i >> 5;
    int x = v;
#pragma unroll
    for (int o = 1; o < 32; o <<= 1) { int y = __shfl_up_sync(~0u, x, o); if (lane >= o) x += y; }
    __shared__ int ws[16];
    if (lane == 31) ws[wid] = x;
    __syncthreads();
    if (wid == 0) {
        int t = (lane < 16) ? ws[lane] : 0;
#pragma unroll
        for (int o = 1; o < 16; o <<= 1) { int y = __shfl_up_sync(~0u, t, o); if (lane >= o) t += y; }
        if (lane < 16) ws[lane] = t;
    }
    __syncthreads();
    int base = wid > 0 ? ws[wid - 1] : 0;
    if (i < NB) g_bsum[i] = x + base - v;
}
__global__ void k_scan3() {
    int i = blockIdx.x * blockDim.x + threadIdx.x;
    if (i < NN) {
        int r = g_rowptr[i] + g_bsum[i >> 8];
        g_rowptr[i] = r;
        g_cursor[i] = r;
    }
    if (i == 0) g_rowptr[NN] = EE;
}
__global__ void k_scatter(const int* __restrict__ src, const int* __restrict__ dst) {
    int e = blockIdx.x * blockDim.x + threadIdx.x;
    if (e >= EE) return;
    int pos = atomicAdd(&g_cursor[dst[e]], 1);
    g_csrc[pos] = src[e];
}

// ---------------- tensor-core GEMM: [NN,K]x[K,64] -> fp16 [NN,64] ----------------
__device__ __forceinline__ void ldsm4(uint32_t a, uint32_t& r0, uint32_t& r1,
                                      uint32_t& r2, uint32_t& r3) {
    asm volatile("ldmatrix.sync.aligned.m8n8.x4.shared.b16 {%0,%1,%2,%3}, [%4];"
                 : "=r"(r0), "=r"(r1), "=r"(r2), "=r"(r3) : "r"(a));
}
__device__ __forceinline__ void ldsm4t(uint32_t a, uint32_t& r0, uint32_t& r1,
                                       uint32_t& r2, uint32_t& r3) {
    asm volatile("ldmatrix.sync.aligned.m8n8.x4.trans.shared.b16 {%0,%1,%2,%3}, [%4];"
                 : "=r"(r0), "=r"(r1), "=r"(r2), "=r"(r3) : "r"(a));
}
__device__ __forceinline__ void mma16816(float* c, const uint32_t* a, uint32_t b0, uint32_t b1) {
    asm volatile("mma.sync.aligned.m16n8k16.row.col.f32.f16.f16.f32 "
                 "{%0,%1,%2,%3}, {%4,%5,%6,%7}, {%8,%9}, {%0,%1,%2,%3};"
                 : "+f"(c[0]), "+f"(c[1]), "+f"(c[2]), "+f"(c[3])
                 : "r"(a[0]), "r"(a[1]), "r"(a[2]), "r"(a[3]), "r"(b0), "r"(b1));
}

// AF32: A fp32 (converted during staging). SCALE: rows *= dinv. ALPHAS: emit GAT scores.
template<int K, int SCALE, int AF32, int ALPHAS>
__global__ void __launch_bounds__(128) k_gemm_mma(const void* __restrict__ Ain,
                                                  const __half* __restrict__ W16,
                                                  __half* __restrict__ O,
                                                  const float* __restrict__ Aps,
                                                  const float* __restrict__ Apd) {
    constexpr int NKB = K / 16;
    __shared__ __align__(16) __half Ws[K * 64];
    __shared__ __align__(16) __half As[2][128 * 24];   // 48B row stride (bank-safe)

    const int tid = threadIdx.x;
    const int lane = tid & 31, w = tid >> 5;
    const int row_blk = blockIdx.x * 128;

    // stage W into smem, XOR-swizzled 16B units: unit(kk,n16) -> kk*8 + (n16^(kk&7))
    for (int u = tid; u < K * 8; u += 128) {
        int kk = u >> 3, n16 = u & 7;
        ((uint4*)Ws)[(kk << 3) | (n16 ^ (kk & 7))] = ((const uint4*)W16)[u];
    }

    auto load_regs = [&](int kb, uint4* r) {
        int grow = row_blk + tid;
        if (AF32) {
            const float4* s = (const float4*)((const float*)Ain + (size_t)grow * K + kb * 16);
            float4 f0, f1, f2, f3;
            if (grow < NN) { f0 = s[0]; f1 = s[1]; f2 = s[2]; f3 = s[3]; }
            else { f0 = f1 = f2 = f3 = make_float4(0.f, 0.f, 0.f, 0.f); }
            r[0] = make_uint4(qpack(f0.x, f0.y), qpack(f0.z, f0.w),
                              qpack(f1.x, f1.y), qpack(f1.z, f1.w));
            r[1] = make_uint4(qpack(f2.x, f2.y), qpack(f2.z, f2.w),
                              qpack(f3.x, f3.y), qpack(f3.z, f3.w));
        } else {
            const uint4* s = (const uint4*)((const __half*)Ain + (size_t)grow * K + kb * 16);
            if (grow < NN) { r[0] = s[0]; r[1] = s[1]; }
            else { r[0] = r[1] = make_uint4(0u, 0u, 0u, 0u); }
        }
    };
    auto store_regs = [&](int buf, const uint4* r) {
        uint4* d = (uint4*)(As[buf] + tid * 24);
        d[0] = r[0]; d[1] = r[1];
    };

    uint4 rg[2];
    load_regs(0, rg);
    store_regs(0, rg);
    __syncthreads();

    float acc[2][8][4];
#pragma unroll
    for (int mi = 0; mi < 2; mi++)
#pragma unroll
        for (int ni = 0; ni < 8; ni++)
#pragma unroll
            for (int q = 0; q < 4; q++) acc[mi][ni][q] = 0.f;

    uint32_t as_u = (uint32_t)__cvta_generic_to_shared(As);
    uint32_t ws_u = (uint32_t)__cvta_generic_to_shared(Ws);

    for (int kb = 0; kb < NKB; kb++) {
        if (kb + 1 < NKB) load_regs(kb + 1, rg);
        int b = kb & 1;
        uint32_t af[2][4];
#pragma unroll
        for (int mi = 0; mi < 2; mi++) {
            uint32_t aa = as_u + b * 6144
                        + (w * 32 + mi * 16 + (lane & 15)) * 48 + ((lane >> 4) << 4);
            ldsm4(aa, af[mi][0], af[mi][1], af[mi][2], af[mi][3]);
        }
        uint32_t bf[4][4];
        int sub = lane >> 3;
        int krow = kb * 16 + ((sub & 1) << 3) + (lane & 7);
#pragma unroll
        for (int g = 0; g < 4; g++) {
            int ucol = g * 2 + (sub >> 1);
            uint32_t ba = ws_u + ((uint32_t)((krow << 3) | (ucol ^ (krow & 7))) << 4);
            ldsm4t(ba, bf[g][0], bf[g][1], bf[g][2], bf[g][3]);
        }
#pragma unroll
        for (int mi = 0; mi < 2; mi++)
#pragma unroll
            for (int ni = 0; ni < 8; ni++) {
                int g = ni >> 1, o = (ni & 1) << 1;
                mma16816(acc[mi][ni], af[mi], bf[g][o], bf[g][o + 1]);
            }
        if (kb + 1 < NKB) {
            store_regs((kb + 1) & 1, rg);
            __syncthreads();
        }
    }

    // epilogue: C frag (c0,c1)=row lane/4, cols 2*(lane%4)+{0,1}; (c2,c3)=row+8
#pragma unroll
    for (int mi = 0; mi < 2; mi++) {
        int r0 = row_blk + w * 32 + mi * 16 + (lane >> 2);
        int r1 = r0 + 8;
        float s0 = 1.f, s1 = 1.f;
        if (SCALE) {
            if (r0 < NN) s0 = g_dinv[r0];
            if (r1 < NN) s1 = g_dinv[r1];
        }
#pragma unroll
        for (int ni = 0; ni < 8; ni++) {
            int c = ni * 8 + (lane & 3) * 2;
            if (r0 < NN) {
                __half2 h = __float22half2_rn(make_float2(acc[mi][ni][0] * s0, acc[mi][ni][1] * s0));
                *(__half2*)(O + (size_t)r0 * FD + c) = h;
            }
            if (r1 < NN) {
                __half2 h = __float22half2_rn(make_float2(acc[mi][ni][2] * s1, acc[mi][ni][3] * s1));
                *(__half2*)(O + (size_t)r1 * FD + c) = h;
            }
            if (ALPHAS) {
                float2 sv = *(const float2*)&Aps[c];
                float2 dv = *(const float2*)&Apd[c];
                float vas0 = acc[mi][ni][0] * sv.x + acc[mi][ni][1] * sv.y;
                float vad0 = acc[mi][ni][0] * dv.x + acc[mi][ni][1] * dv.y;
                float vas1 = acc[mi][ni][2] * sv.x + acc[mi][ni][3] * sv.y;
                float vad1 = acc[mi][ni][2] * dv.x + acc[mi][ni][3] * dv.y;
#pragma unroll
                for (int o = 1; o < 4; o <<= 1) {
                    vas0 += __shfl_xor_sync(0xffffffffu, vas0, o);
                    vad0 += __shfl_xor_sync(0xffffffffu, vad0, o);
                    vas1 += __shfl_xor_sync(0xffffffffu, vas1, o);
                    vad1 += __shfl_xor_sync(0xffffffffu, vad1, o);
                }
                if ((lane & 3) == 0) {
                    if (r0 < NN) { g_as[r0 * NHD + ni] = vas0; g_ad[r0 * NHD + ni] = vad0; }
                    if (r1 < NN) { g_as[r1 * NHD + ni] = vas1; g_ad[r1 * NHD + ni] = vad1; }
                }
            }
        }
    }
}

// ---------------- GCN gather (warp per node, fp16 messages) ----------------
template<int HOUT>
__global__ void __launch_bounds__(256) k_gcn_gather(const __half* __restrict__ ts,
                                                    void* __restrict__ outv,
                                                    const float* __restrict__ b,
                                                    int do_relu) {
    int warp = (blockIdx.x * blockDim.x + threadIdx.x) >> 5;
    int lane = threadIdx.x & 31;
    if (warp >= NN) return;
    int d = warp;
    int beg = g_rowptr[d], end = g_rowptr[d + 1];
    float2 acc = __half22float2(((const __half2*)(ts + (size_t)d * FD))[lane]);
    for (int base = beg; base < end; base += 32) {
        int n = min(32, end - base);
        int s_l = (lane < n) ? g_csrc[base + lane] : 0;
        for (int j = 0; j < n; j++) {
            int s = __shfl_sync(0xffffffffu, s_l, j);
            float2 v = __half22float2(((const __half2*)(ts + (size_t)s * FD))[lane]);
            acc.x += v.x; acc.y += v.y;
        }
    }
    float nv = g_dinv[d];
    float2 bb = ((const float2*)b)[lane];
    float ox = acc.x * nv + bb.x, oy = acc.y * nv + bb.y;
    if (do_relu) { ox = fmaxf(ox, 0.f); oy = fmaxf(oy, 0.f); }
    if (HOUT) {
        ((__half2*)((__half*)outv + (size_t)d * FD))[lane] = __float22half2_rn(make_float2(ox, oy));
    } else {
        ((float2*)((float*)outv + (size_t)d * FD))[lane] = make_float2(ox, oy);
    }
}

// ---------------- single-pass GAT (no max subtraction; scores are small) ----------------
__global__ void __launch_bounds__(256) k_gat1(const __half* __restrict__ hg,
                                              __half* __restrict__ out,
                                              const float* __restrict__ bg) {
    int warp = (blockIdx.x * blockDim.x + threadIdx.x) >> 5;
    int lane = threadIdx.x & 31;
    if (warp >= NN) return;
    int d = warp;
    int beg = g_rowptr[d], end = g_rowptr[d + 1];
    int hmy = lane >> 2;   // head owning this lane's feature pair

    // scoring lanes: lane h ∈ [0,8) handles head h
    float ad_l = 0.f, z_l = 0.f, p_self = 0.f;
    if (lane < NHD) {
        ad_l = g_ad[(size_t)d * NHD + lane];
        float as_d = g_as[(size_t)d * NHD + lane];
        p_self = __expf(lrelu(as_d + ad_l));
        z_l = p_self;
    }
    float pself_my = __shfl_sync(0xffffffffu, p_self, hmy);
    float2 hv = __half22float2(((const __half2*)(hg + (size_t)d * FD))[lane]);
    float2 acc = make_float2(pself_my * hv.x, pself_my * hv.y);

    for (int base = beg; base < end; base += 32) {
        int n = min(32, end - base);
        int s_l = (lane < n) ? g_csrc[base + lane] : 0;
        for (int j = 0; j < n; j++) {
            int s = __shfl_sync(0xffffffffu, s_l, j);
            float p = 0.f;
            if (lane < NHD) {
                float asv = g_as[(size_t)s * NHD + lane];
                p = __expf(lrelu(asv + ad_l));
                z_l += p;
            }
            float pmy = __shfl_sync(0xffffffffu, p, hmy);
            float2 v = __half22float2(((const __half2*)(hg + (size_t)s * FD))[lane]);
            acc.x += pmy * v.x; acc.y += pmy * v.y;
        }
    }
    float zi_l = (lane < NHD) ? (1.0f / z_l) : 0.f;
    float zi_my = __shfl_sync(0xffffffffu, zi_l, hmy);

    float2 bb = ((const float2*)bg)[lane];
    float ox = fmaxf(acc.x * zi_my + bb.x, 0.f);
    float oy = fmaxf(acc.y * zi_my + bb.y, 0.f);
    ((__half2*)(out + (size_t)d * FD))[lane] = __float22half2_rn(make_float2(ox, oy));
}

// ---------------- driver ----------------
extern "C" void kernel_launch(void* const* d_in, const int* in_sizes, int n_in,
                              void* d_out, int out_size) {
    const float* x    = (const float*)d_in[0];
    const int*   ei   = (const int*)d_in[1];
    const float* W0   = (const float*)d_in[2];
    const float* b0   = (const float*)d_in[3];
    const float* Wg   = (const float*)d_in[4];
    const float* Asrc = (const float*)d_in[5];
    const float* Adst = (const float*)d_in[6];
    const float* bg   = (const float*)d_in[7];
    const float* W2   = (const float*)d_in[8];
    const float* b2   = (const float*)d_in[9];
    const float* W3   = (const float*)d_in[10];
    const float* b3   = (const float*)d_in[11];
    const int* src = ei;
    const int* dst = ei + EE;

    __half* t16; cudaGetSymbolAddress((void**)&t16, g_t);
    __half* h16; cudaGetSymbolAddress((void**)&h16, g_h);
    __half* w16; cudaGetSymbolAddress((void**)&w16, g_w16);
    float* outp = (float*)d_out;

    const int T = 256;
    const int gN    = CDIV(NN, T);
    const int gE    = CDIV(EE, T);
    const int gGemm = CDIV(NN, 128);
    const int gWarp = CDIV(NN * 32, T);

    // ---- weight conversion (+deg zero) + CSR build ----
    k_w2h<<<gN, T>>>(W0, Wg, W2, W3);
    k_deg<<<gE, T>>>(dst);
    k_scan1<<<NB, 256>>>();
    k_scan2<<<1, 512>>>();
    k_scan3<<<gN, T>>>();
    k_scatter<<<gE, T>>>(src, dst);

    // ---- layer 0: GCN(128->64) + relu ----
    k_gemm_mma<128, 1, 1, 0><<<gGemm, 128>>>(x, w16, t16, nullptr, nullptr);
    k_gcn_gather<1><<<gWarp, T>>>(t16, h16, b0, 1);

    // ---- layer 1: GAT(64 -> 8x8 concat) + relu; alphas fused into GEMM epilogue ----
    k_gemm_mma<64, 0, 0, 1><<<gGemm, 128>>>(h16, w16 + 8192, t16, Asrc, Adst);
    k_gat1<<<gWarp, T>>>(t16, h16, bg);

    // ---- layer 2: GCN(64->64) + relu ----
    k_gemm_mma<64, 1, 0, 0><<<gGemm, 128>>>(h16, w16 + 12288, t16, nullptr, nullptr);
    k_gcn_gather<1><<<gWarp, T>>>(t16, h16, b2, 1);

    // ---- layer 3: GCN(64->64) into d_out, no relu ----
    k_gemm_mma<64, 1, 0, 0><<<gGemm, 128>>>(h16, w16 + 16384, t16, nullptr, nullptr);
    k_gcn_gather<0><<<gWarp, T>>>(t16, outp, b3, 0);
}

// round 11
// speedup vs baseline: 3.7567x; 1.1398x over previous
#include <cuda_runtime.h>
#include <cuda_fp16.h>
#include <cstdint>

#define NN 100000
#define EE 1600000
#define FD 64
#define NHD 8
#define NB  391               // CDIV(NN,256) scan blocks
#define CDIV(a,b) (((a)+(b)-1)/(b))

// ---------------- scratch ----------------
static __device__ __align__(16) float  g_dinv[NN];
static __device__ __align__(16) __half g_t  [NN*FD];     // GEMM output (messages)
static __device__ __align__(16) __half g_h  [NN*FD];     // layer activations (fp16)
static __device__ __align__(16) __half g_w16[20480];     // W0(8192) Wg(4096) W2(4096) W3(4096)
static __device__ __align__(16) float  g_as [NN*NHD];
static __device__ __align__(16) float  g_ad [NN*NHD];
static __device__ int g_deg[NN];
static __device__ int g_rowptr[NN+1];
static __device__ int g_cursor[NN];
static __device__ int g_csrc[EE];
static __device__ int g_bsum[512];

__device__ __forceinline__ float lrelu(float x) { return x > 0.f ? x : 0.2f * x; }
__device__ __forceinline__ uint32_t qpack(float a, float b) {
    __half2 h = __float22half2_rn(make_float2(a, b));
    return *(uint32_t*)&h;
}

// ---------------- weight conversion + degree zero ----------------
__global__ void k_w2h(const float* __restrict__ W0, const float* __restrict__ Wg,
                      const float* __restrict__ W2, const float* __restrict__ W3) {
    int i = blockIdx.x * blockDim.x + threadIdx.x;
    if (i < NN) g_deg[i] = 0;
    if (i < 8192) g_w16[i] = __float2half(W0[i]);
    if (i < 4096) {
        g_w16[8192  + i] = __float2half(Wg[i]);
        g_w16[12288 + i] = __float2half(W2[i]);
        g_w16[16384 + i] = __float2half(W3[i]);
    }
}

// ---------------- CSR build ----------------
__global__ void k_deg(const int* __restrict__ dst) {
    int e = blockIdx.x * blockDim.x + threadIdx.x;
    if (e < EE) atomicAdd(&g_deg[dst[e]], 1);
}
__global__ void __launch_bounds__(256) k_scan1() {
    int i = blockIdx.x * 256 + threadIdx.x;
    int v = (i < NN) ? g_deg[i] : 0;
    if (i < NN) g_dinv[i] = rsqrtf((float)(v + 1));
    int lane = threadIdx.x & 31, wid = threadIdx.x >> 5;
    int x = v;
#pragma unroll
    for (int o = 1; o < 32; o <<= 1) { int y = __shfl_up_sync(~0u, x, o); if (lane >= o) x += y; }
    __shared__ int ws[8];
    if (lane == 31) ws[wid] = x;
    __syncthreads();
    if (wid == 0) {
        int t = (lane < 8) ? ws[lane] : 0;
#pragma unroll
        for (int o = 1; o < 8; o <<= 1) { int y = __shfl_up_sync(~0u, t, o); if (lane >= o) t += y; }
        if (lane < 8) ws[lane] = t;
    }
    __syncthreads();
    int base = wid > 0 ? ws[wid - 1] : 0;
    int incl = x + base;
    if (i < NN) g_rowptr[i] = incl - v;
    if (threadIdx.x == 255) g_bsum[blockIdx.x] = incl;
}
__global__ void __launch_bounds__(512) k_scan2() {
    int i = threadIdx.x;
    int v = (i < NB) ? g_bsum[i] : 0;
    int lane = i & 31, wid = i >> 5;
    int x = v;
#pragma unroll
    for (int o = 1; o < 32; o <<= 1) { int y = __shfl_up_sync(~0u, x, o); if (lane >= o) x += y; }
    __shared__ int ws[16];
    if (lane == 31) ws[wid] = x;
    __syncthreads();
    if (wid == 0) {
        int t = (lane < 16) ? ws[lane] : 0;
#pragma unroll
        for (int o = 1; o < 16; o <<= 1) { int y = __shfl_up_sync(~0u, t, o); if (lane >= o) t += y; }
        if (lane < 16) ws[lane] = t;
    }
    __syncthreads();
    int base = wid > 0 ? ws[wid - 1] : 0;
    if (i < NB) g_bsum[i] = x + base - v;
}
__global__ void k_scan3() {
    int i = blockIdx.x * blockDim.x + threadIdx.x;
    if (i < NN) {
        int r = g_rowptr[i] + g_bsum[i >> 8];
        g_rowptr[i] = r;
        g_cursor[i] = r;
    }
    if (i == 0) g_rowptr[NN] = EE;
}
__global__ void k_scatter(const int* __restrict__ src, const int* __restrict__ dst) {
    int e = blockIdx.x * blockDim.x + threadIdx.x;
    if (e >= EE) return;
    int pos = atomicAdd(&g_cursor[dst[e]], 1);
    g_csrc[pos] = src[e];
}

// ---------------- tensor-core GEMM: [NN,K]x[K,64] -> fp16 [NN,64] ----------------
__device__ __forceinline__ void ldsm4(uint32_t a, uint32_t& r0, uint32_t& r1,
                                      uint32_t& r2, uint32_t& r3) {
    asm volatile("ldmatrix.sync.aligned.m8n8.x4.shared.b16 {%0,%1,%2,%3}, [%4];"
                 : "=r"(r0), "=r"(r1), "=r"(r2), "=r"(r3) : "r"(a));
}
__device__ __forceinline__ void ldsm4t(uint32_t a, uint32_t& r0, uint32_t& r1,
                                       uint32_t& r2, uint32_t& r3) {
    asm volatile("ldmatrix.sync.aligned.m8n8.x4.trans.shared.b16 {%0,%1,%2,%3}, [%4];"
                 : "=r"(r0), "=r"(r1), "=r"(r2), "=r"(r3) : "r"(a));
}
__device__ __forceinline__ void mma16816(float* c, const uint32_t* a, uint32_t b0, uint32_t b1) {
    asm volatile("mma.sync.aligned.m16n8k16.row.col.f32.f16.f16.f32 "
                 "{%0,%1,%2,%3}, {%4,%5,%6,%7}, {%8,%9}, {%0,%1,%2,%3};"
                 : "+f"(c[0]), "+f"(c[1]), "+f"(c[2]), "+f"(c[3])
                 : "r"(a[0]), "r"(a[1]), "r"(a[2]), "r"(a[3]), "r"(b0), "r"(b1));
}

// AF32: A fp32 (converted during staging). SCALE: rows *= dinv. ALPHAS: emit GAT scores.
template<int K, int SCALE, int AF32, int ALPHAS>
__global__ void __launch_bounds__(128) k_gemm_mma(const void* __restrict__ Ain,
                                                  const __half* __restrict__ W16,
                                                  __half* __restrict__ O,
                                                  const float* __restrict__ Aps,
                                                  const float* __restrict__ Apd) {
    constexpr int NKB = K / 16;
    __shared__ __align__(16) __half Ws[K * 64];
    __shared__ __align__(16) __half As[2][128 * 24];   // 48B row stride (bank-safe)

    const int tid = threadIdx.x;
    const int lane = tid & 31, w = tid >> 5;
    const int row_blk = blockIdx.x * 128;

    // stage W into smem, XOR-swizzled 16B units: unit(kk,n16) -> kk*8 + (n16^(kk&7))
    for (int u = tid; u < K * 8; u += 128) {
        int kk = u >> 3, n16 = u & 7;
        ((uint4*)Ws)[(kk << 3) | (n16 ^ (kk & 7))] = ((const uint4*)W16)[u];
    }

    auto load_regs = [&](int kb, uint4* r) {
        int grow = row_blk + tid;
        if (AF32) {
            const float4* s = (const float4*)((const float*)Ain + (size_t)grow * K + kb * 16);
            float4 f0, f1, f2, f3;
            if (grow < NN) { f0 = s[0]; f1 = s[1]; f2 = s[2]; f3 = s[3]; }
            else { f0 = f1 = f2 = f3 = make_float4(0.f, 0.f, 0.f, 0.f); }
            r[0] = make_uint4(qpack(f0.x, f0.y), qpack(f0.z, f0.w),
                              qpack(f1.x, f1.y), qpack(f1.z, f1.w));
            r[1] = make_uint4(qpack(f2.x, f2.y), qpack(f2.z, f2.w),
                              qpack(f3.x, f3.y), qpack(f3.z, f3.w));
        } else {
            const uint4* s = (const uint4*)((const __half*)Ain + (size_t)grow * K + kb * 16);
            if (grow < NN) { r[0] = s[0]; r[1] = s[1]; }
            else { r[0] = r[1] = make_uint4(0u, 0u, 0u, 0u); }
        }
    };
    auto store_regs = [&](int buf, const uint4* r) {
        uint4* d = (uint4*)(As[buf] + tid * 24);
        d[0] = r[0]; d[1] = r[1];
    };

    uint4 rg[2];
    load_regs(0, rg);
    store_regs(0, rg);
    __syncthreads();

    float acc[2][8][4];
#pragma unroll
    for (int mi = 0; mi < 2; mi++)
#pragma unroll
        for (int ni = 0; ni < 8; ni++)
#pragma unroll
            for (int q = 0; q < 4; q++) acc[mi][ni][q] = 0.f;

    uint32_t as_u = (uint32_t)__cvta_generic_to_shared(As);
    uint32_t ws_u = (uint32_t)__cvta_generic_to_shared(Ws);

    for (int kb = 0; kb < NKB; kb++) {
        if (kb + 1 < NKB) load_regs(kb + 1, rg);
        int b = kb & 1;
        uint32_t af[2][4];
#pragma unroll
        for (int mi = 0; mi < 2; mi++) {
            uint32_t aa = as_u + b * 6144
                        + (w * 32 + mi * 16 + (lane & 15)) * 48 + ((lane >> 4) << 4);
            ldsm4(aa, af[mi][0], af[mi][1], af[mi][2], af[mi][3]);
        }
        uint32_t bf[4][4];
        int sub = lane >> 3;
        int krow = kb * 16 + ((sub & 1) << 3) + (lane & 7);
#pragma unroll
        for (int g = 0; g < 4; g++) {
            int ucol = g * 2 + (sub >> 1);
            uint32_t ba = ws_u + ((uint32_t)((krow << 3) | (ucol ^ (krow & 7))) << 4);
            ldsm4t(ba, bf[g][0], bf[g][1], bf[g][2], bf[g][3]);
        }
#pragma unroll
        for (int mi = 0; mi < 2; mi++)
#pragma unroll
            for (int ni = 0; ni < 8; ni++) {
                int g = ni >> 1, o = (ni & 1) << 1;
                mma16816(acc[mi][ni], af[mi], bf[g][o], bf[g][o + 1]);
            }
        if (kb + 1 < NKB) {
            store_regs((kb + 1) & 1, rg);
            __syncthreads();
        }
    }

    // epilogue: C frag (c0,c1)=row lane/4, cols 2*(lane%4)+{0,1}; (c2,c3)=row+8
#pragma unroll
    for (int mi = 0; mi < 2; mi++) {
        int r0 = row_blk + w * 32 + mi * 16 + (lane >> 2);
        int r1 = r0 + 8;
        float s0 = 1.f, s1 = 1.f;
        if (SCALE) {
            if (r0 < NN) s0 = g_dinv[r0];
            if (r1 < NN) s1 = g_dinv[r1];
        }
#pragma unroll
        for (int ni = 0; ni < 8; ni++) {
            int c = ni * 8 + (lane & 3) * 2;
            if (r0 < NN) {
                __half2 h = __float22half2_rn(make_float2(acc[mi][ni][0] * s0, acc[mi][ni][1] * s0));
                *(__half2*)(O + (size_t)r0 * FD + c) = h;
            }
            if (r1 < NN) {
                __half2 h = __float22half2_rn(make_float2(acc[mi][ni][2] * s1, acc[mi][ni][3] * s1));
                *(__half2*)(O + (size_t)r1 * FD + c) = h;
            }
            if (ALPHAS) {
                float2 sv = *(const float2*)&Aps[c];
                float2 dv = *(const float2*)&Apd[c];
                float vas0 = acc[mi][ni][0] * sv.x + acc[mi][ni][1] * sv.y;
                float vad0 = acc[mi][ni][0] * dv.x + acc[mi][ni][1] * dv.y;
                float vas1 = acc[mi][ni][2] * sv.x + acc[mi][ni][3] * sv.y;
                float vad1 = acc[mi][ni][2] * dv.x + acc[mi][ni][3] * dv.y;
#pragma unroll
                for (int o = 1; o < 4; o <<= 1) {
                    vas0 += __shfl_xor_sync(0xffffffffu, vas0, o);
                    vad0 += __shfl_xor_sync(0xffffffffu, vad0, o);
                    vas1 += __shfl_xor_sync(0xffffffffu, vas1, o);
                    vad1 += __shfl_xor_sync(0xffffffffu, vad1, o);
                }
                if ((lane & 3) == 0) {
                    if (r0 < NN) { g_as[r0 * NHD + ni] = vas0; g_ad[r0 * NHD + ni] = vad0; }
                    if (r1 < NN) { g_as[r1 * NHD + ni] = vas1; g_ad[r1 * NHD + ni] = vad1; }
                }
            }
        }
    }
}

// ---------------- GCN gather v2: warp per node, 4 edge groups x 8 feature lanes ----------------
// lane = eg*8 + f; group eg processes edges beg+eg, beg+eg+4, ...; lane f covers halfs 8f..8f+7.
template<int HOUT>
__global__ void __launch_bounds__(256) k_gcn_gather(const __half* __restrict__ ts,
                                                    void* __restrict__ outv,
                                                    const float* __restrict__ b,
                                                    int do_relu) {
    int warp = (blockIdx.x * blockDim.x + threadIdx.x) >> 5;
    int lane = threadIdx.x & 31;
    if (warp >= NN) return;
    int d = warp;
    int f = lane & 7, eg = lane >> 3;
    int beg = g_rowptr[d], end = g_rowptr[d + 1];

    float acc[8];
#pragma unroll
    for (int i = 0; i < 8; i++) acc[i] = 0.f;
    if (eg == 0) {   // self term
        uint4 hv = *(const uint4*)(ts + (size_t)d * FD + f * 8);
        const __half2* hp = (const __half2*)&hv;
#pragma unroll
        for (int i = 0; i < 4; i++) {
            float2 v = __half22float2(hp[i]);
            acc[i * 2] += v.x; acc[i * 2 + 1] += v.y;
        }
    }

    int niter = (end - beg + 3) >> 2;
    int idx = beg + eg;
    int s = (idx < end) ? g_csrc[idx] : -1;
    for (int t = 0; t < niter; t++) {
        int idx2 = idx + 4;
        int s2 = (idx2 < end) ? g_csrc[idx2] : -1;
        if (s >= 0) {
            uint4 v = *(const uint4*)(ts + (size_t)s * FD + f * 8);
            const __half2* hp = (const __half2*)&v;
#pragma unroll
            for (int i = 0; i < 4; i++) {
                float2 w = __half22float2(hp[i]);
                acc[i * 2] += w.x; acc[i * 2 + 1] += w.y;
            }
        }
        s = s2; idx = idx2;
    }

    // merge the 4 edge groups (lanes with equal f)
#pragma unroll
    for (int i = 0; i < 8; i++) {
        acc[i] += __shfl_xor_sync(0xffffffffu, acc[i], 8);
        acc[i] += __shfl_xor_sync(0xffffffffu, acc[i], 16);
    }

    if (eg == 0) {
        float nv = g_dinv[d];
        float4 b0 = ((const float4*)b)[f * 2];
        float4 b1 = ((const float4*)b)[f * 2 + 1];
        float o[8];
        o[0] = acc[0] * nv + b0.x; o[1] = acc[1] * nv + b0.y;
        o[2] = acc[2] * nv + b0.z; o[3] = acc[3] * nv + b0.w;
        o[4] = acc[4] * nv + b1.x; o[5] = acc[5] * nv + b1.y;
        o[6] = acc[6] * nv + b1.z; o[7] = acc[7] * nv + b1.w;
        if (do_relu) {
#pragma unroll
            for (int i = 0; i < 8; i++) o[i] = fmaxf(o[i], 0.f);
        }
        if (HOUT) {
            uint4 pk = make_uint4(qpack(o[0], o[1]), qpack(o[2], o[3]),
                                  qpack(o[4], o[5]), qpack(o[6], o[7]));
            *(uint4*)((__half*)outv + (size_t)d * FD + f * 8) = pk;
        } else {
            float* op = (float*)outv + (size_t)d * FD + f * 8;
            *(float4*)op       = make_float4(o[0], o[1], o[2], o[3]);
            *(float4*)(op + 4) = make_float4(o[4], o[5], o[6], o[7]);
        }
    }
}

// ---------------- single-pass GAT v2: 4 edge groups x 8 lanes; lane f = head f ----------------
__global__ void __launch_bounds__(256) k_gat1(const __half* __restrict__ hg,
                                              __half* __restrict__ out,
                                              const float* __restrict__ bg) {
    int warp = (blockIdx.x * blockDim.x + threadIdx.x) >> 5;
    int lane = threadIdx.x & 31;
    if (warp >= NN) return;
    int d = warp;
    int f = lane & 7, eg = lane >> 3;
    int beg = g_rowptr[d], end = g_rowptr[d + 1];

    float ad_f = g_ad[(size_t)d * NHD + f];
    float acc[8];
#pragma unroll
    for (int i = 0; i < 8; i++) acc[i] = 0.f;
    float z = 0.f;
    if (eg == 0) {   // self loop
        float as_d = g_as[(size_t)d * NHD + f];
        float ps = __expf(lrelu(as_d + ad_f));
        z = ps;
        uint4 hv = *(const uint4*)(hg + (size_t)d * FD + f * 8);
        const __half2* hp = (const __half2*)&hv;
#pragma unroll
        for (int i = 0; i < 4; i++) {
            float2 v = __half22float2(hp[i]);
            acc[i * 2] += ps * v.x; acc[i * 2 + 1] += ps * v.y;
        }
    }

    int niter = (end - beg + 3) >> 2;
    int idx = beg + eg;
    int s = (idx < end) ? g_csrc[idx] : -1;
    for (int t = 0; t < niter; t++) {
        int idx2 = idx + 4;
        int s2 = (idx2 < end) ? g_csrc[idx2] : -1;
        if (s >= 0) {
            float asv = g_as[(size_t)s * NHD + f];
            uint4 v = *(const uint4*)(hg + (size_t)s * FD + f * 8);
            float p = __expf(lrelu(asv + ad_f));
            z += p;
            const __half2* hp = (const __half2*)&v;
#pragma unroll
            for (int i = 0; i < 4; i++) {
                float2 w = __half22float2(hp[i]);
                acc[i * 2] += p * w.x; acc[i * 2 + 1] += p * w.y;
            }
        }
        s = s2; idx = idx2;
    }

    // merge the 4 edge groups
    z += __shfl_xor_sync(0xffffffffu, z, 8);
    z += __shfl_xor_sync(0xffffffffu, z, 16);
#pragma unroll
    for (int i = 0; i < 8; i++) {
        acc[i] += __shfl_xor_sync(0xffffffffu, acc[i], 8);
        acc[i] += __shfl_xor_sync(0xffffffffu, acc[i], 16);
    }

    if (eg == 0) {
        float zi = 1.0f / z;
        float4 b0 = ((const float4*)bg)[f * 2];
        float4 b1 = ((const float4*)bg)[f * 2 + 1];
        float o[8];
        o[0] = fmaxf(acc[0] * zi + b0.x, 0.f); o[1] = fmaxf(acc[1] * zi + b0.y, 0.f);
        o[2] = fmaxf(acc[2] * zi + b0.z, 0.f); o[3] = fmaxf(acc[3] * zi + b0.w, 0.f);
        o[4] = fmaxf(acc[4] * zi + b1.x, 0.f); o[5] = fmaxf(acc[5] * zi + b1.y, 0.f);
        o[6] = fmaxf(acc[6] * zi + b1.z, 0.f); o[7] = fmaxf(acc[7] * zi + b1.w, 0.f);
        uint4 pk = make_uint4(qpack(o[0], o[1]), qpack(o[2], o[3]),
                              qpack(o[4], o[5]), qpack(o[6], o[7]));
        *(uint4*)(out + (size_t)d * FD + f * 8) = pk;
    }
}

// ---------------- driver ----------------
extern "C" void kernel_launch(void* const* d_in, const int* in_sizes, int n_in,
                              void* d_out, int out_size) {
    const float* x    = (const float*)d_in[0];
    const int*   ei   = (const int*)d_in[1];
    const float* W0   = (const float*)d_in[2];
    const float* b0   = (const float*)d_in[3];
    const float* Wg   = (const float*)d_in[4];
    const float* Asrc = (const float*)d_in[5];
    const float* Adst = (const float*)d_in[6];
    const float* bg   = (const float*)d_in[7];
    const float* W2   = (const float*)d_in[8];
    const float* b2   = (const float*)d_in[9];
    const float* W3   = (const float*)d_in[10];
    const float* b3   = (const float*)d_in[11];
    const int* src = ei;
    const int* dst = ei + EE;

    __half* t16; cudaGetSymbolAddress((void**)&t16, g_t);
    __half* h16; cudaGetSymbolAddress((void**)&h16, g_h);
    __half* w16; cudaGetSymbolAddress((void**)&w16, g_w16);
    float* outp = (float*)d_out;

    const int T = 256;
    const int gN    = CDIV(NN, T);
    const int gE    = CDIV(EE, T);
    const int gGemm = CDIV(NN, 128);
    const int gWarp = CDIV(NN * 32, T);

    // ---- weight conversion (+deg zero) + CSR build ----
    k_w2h<<<gN, T>>>(W0, Wg, W2, W3);
    k_deg<<<gE, T>>>(dst);
    k_scan1<<<NB, 256>>>();
    k_scan2<<<1, 512>>>();
    k_scan3<<<gN, T>>>();
    k_scatter<<<gE, T>>>(src, dst);

    // ---- layer 0: GCN(128->64) + relu ----
    k_gemm_mma<128, 1, 1, 0><<<gGemm, 128>>>(x, w16, t16, nullptr, nullptr);
    k_gcn_gather<1><<<gWarp, T>>>(t16, h16, b0, 1);

    // ---- layer 1: GAT(64 -> 8x8 concat) + relu; alphas fused into GEMM epilogue ----
    k_gemm_mma<64, 0, 0, 1><<<gGemm, 128>>>(h16, w16 + 8192, t16, Asrc, Adst);
    k_gat1<<<gWarp, T>>>(t16, h16, bg);

    // ---- layer 2: GCN(64->64) + relu ----
    k_gemm_mma<64, 1, 0, 0><<<gGemm, 128>>>(h16, w16 + 12288, t16, nullptr, nullptr);
    k_gcn_gather<1><<<gWarp, T>>>(t16, h16, b2, 1);

    // ---- layer 3: GCN(64->64) into d_out, no relu ----
    k_gemm_mma<64, 1, 0, 0><<<gGemm, 128>>>(h16, w16 + 16384, t16, nullptr, nullptr);
    k_gcn_gather<0><<<gWarp, T>>>(t16, outp, b3, 0);
}